// round 11
// baseline (speedup 1.0000x reference)
#include <cuda_runtime.h>
#include <math.h>
#include <stdint.h>

// ---------------------------------------------------------------------------
// VQ-VAE forward. 3x3 convs, enc2 (4x4 s2), tc1 (convT 4x4 s2) via
// split-precision TF32 mma.sync implicit GEMM; rest fp32 FFMA2.
// Output layout (float32, 3145732 elems):
//   [0] e_and_q  [1..3145728] x_recon  [3145729] e_latent  [3145730] q_latent
//   [3145731] est_words
// ---------------------------------------------------------------------------

#define BATCH 64
#define VQ_K 512
#define VQ_D 64
#define OUT_RECON_OFF 1
#define OUT_RECON_N   (64*3*128*128)
#define OUT_ELQ  (OUT_RECON_OFF + OUT_RECON_N)
#define OUT_QLQ  (OUT_ELQ + 1)
#define OUT_EW   (OUT_QLQ + 1)

typedef unsigned long long ull;

// ---- packed f32x2 helpers --------------------------------------------------
__device__ __forceinline__ ull pk2(float lo, float hi) {
    ull r; asm("mov.b64 %0, {%1, %2};" : "=l"(r) : "f"(lo), "f"(hi)); return r;
}
__device__ __forceinline__ float2 unpk(ull v) {
    float2 r; asm("mov.b64 {%0, %1}, %2;" : "=f"(r.x), "=f"(r.y) : "l"(v)); return r;
}
__device__ __forceinline__ void fma2(ull& d, ull a, ull b) {
    asm("fma.rn.f32x2 %0, %1, %2, %0;" : "+l"(d) : "l"(a), "l"(b));
}

// ---- tf32 helpers ----------------------------------------------------------
__device__ __forceinline__ float tf32_rna(float x) {
    unsigned u; asm("cvt.rna.tf32.f32 %0, %1;" : "=r"(u) : "f"(x));
    return __uint_as_float(u);
}
__device__ __forceinline__ void mma_tf32(float* d, const unsigned* a, const unsigned* b) {
    asm volatile(
        "mma.sync.aligned.m16n8k8.row.col.f32.tf32.tf32.f32 "
        "{%0,%1,%2,%3}, {%4,%5,%6,%7}, {%8,%9}, {%0,%1,%2,%3};\n"
        : "+f"(d[0]), "+f"(d[1]), "+f"(d[2]), "+f"(d[3])
        : "r"(a[0]), "r"(a[1]), "r"(a[2]), "r"(a[3]), "r"(b[0]), "r"(b[1]));
}

// ---------------- scratch buffers -------------------------------------------
__device__ float g_h1 [64*64*64*64];
__device__ float g_a  [64*128*32*32];
__device__ float g_b  [64*128*32*32];
__device__ float g_mid[64*64*32*32];
__device__ float g_ze [64*64*32*32];
__device__ float g_zq [64*64*32*32];
__device__ float g_wh [128*128*9];     // split weights (hi)
__device__ float g_wl [128*128*9];     // split weights (lo)
__device__ int   g_hist[VQ_K];
__device__ float g_mse[1];

__global__ void reset_k(int* hist, float* mse) {
    int t = threadIdx.x;
    if (t < VQ_K) hist[t] = 0;
    if (t == 0)   mse[0] = 0.f;
}

// ---------------------------------------------------------------------------
// Weight pre-splits.
// ---------------------------------------------------------------------------
// 3x3 conv, OIHW -> [tap*CIN+ci][oc]
__global__ void wsplit_k(const float* __restrict__ w, int CIN, int COUT,
                         float* __restrict__ wh, float* __restrict__ wl)
{
    int total = COUT * CIN * 9;
    for (int j = blockIdx.x * blockDim.x + threadIdx.x; j < total;
         j += gridDim.x * blockDim.x) {
        int row = j / COUT;
        int oc  = j - row * COUT;
        int tap = row / CIN;
        int ci  = row - tap * CIN;
        float v = w[((size_t)oc * CIN + ci) * 9 + tap];
        float hi = tf32_rna(v);
        wh[j] = hi;
        wl[j] = tf32_rna(v - hi);
    }
}

// 4x4 conv, OIHW -> [tap*CIN+ci][oc], tap = kh*4+kw
__global__ void wsplit4_k(const float* __restrict__ w, int CIN, int COUT,
                          float* __restrict__ wh, float* __restrict__ wl)
{
    int total = COUT * CIN * 16;
    for (int j = blockIdx.x * blockDim.x + threadIdx.x; j < total;
         j += gridDim.x * blockDim.x) {
        int row = j / COUT;
        int oc  = j - row * COUT;
        int tap = row / CIN;
        int ci  = row - tap * CIN;
        float v = w[((size_t)oc * CIN + ci) * 16 + tap];
        float hi = tf32_rna(v);
        wh[j] = hi;
        wl[j] = tf32_rna(v - hi);
    }
}

// convT 4x4, (CIN,COUT,kh,kw) -> [(class*4+tap)*CIN+ci][oc]
// class = po*2+pw (output parities), tap = khi*2+kwi,
// kh = ((po+1)&1)+2*khi, kw = ((pw+1)&1)+2*kwi
__global__ void wsplitT_k(const float* __restrict__ w, int CIN, int COUT,
                          float* __restrict__ wh, float* __restrict__ wl)
{
    int total = 16 * CIN * COUT;
    for (int j = blockIdx.x * blockDim.x + threadIdx.x; j < total;
         j += gridDim.x * blockDim.x) {
        int row = j / COUT;
        int oc  = j - row * COUT;
        int ct  = row / CIN;
        int ci  = row - ct * CIN;
        int cls = ct >> 2, tap = ct & 3;
        int po = cls >> 1, pw = cls & 1;
        int kh = ((po + 1) & 1) + 2 * (tap >> 1);
        int kw = ((pw + 1) & 1) + 2 * (tap & 1);
        float v = w[((size_t)ci * COUT + oc) * 16 + kh * 4 + kw];
        float hi = tf32_rna(v);
        wh[j] = hi;
        wl[j] = tf32_rna(v - hi);
    }
}

// ---------------------------------------------------------------------------
// 3x3 stride-1 pad-1 conv on 32x32 via split-TF32 mma (3xTF32).
// grid(COUT/64, 8, B), block 256. CTA tile M=128 (4 rows x 32), N=64.
// smem: A hi/lo [8ci][6r][36c]; B hi/lo [72][72].
// ---------------------------------------------------------------------------
#define A_PLANE 1728
#define B_PLANE 5184
#define SM3_BYTES ((2*A_PLANE + 2*B_PLANE) * 4)    // 55296

template<int CIN, int COUT, bool PRE, bool POST, bool BIAS>
__global__ void __launch_bounds__(256, 2) conv3x3_mma_k(
    const float* __restrict__ in, const float* __restrict__ wh,
    const float* __restrict__ wl, const float* __restrict__ bias,
    float* __restrict__ out)
{
    extern __shared__ float smx[];
    float* sAh = smx;
    float* sAl = smx + A_PLANE;
    float* sBh = smx + 2 * A_PLANE;
    float* sBl = smx + 2 * A_PLANE + B_PLANE;

    const int n    = blockIdx.z;
    const int oc0  = blockIdx.x * 64;
    const int r0g  = blockIdx.y * 4;
    const int tid  = threadIdx.x;
    const int warp = tid >> 5;
    const int lane = tid & 31;
    const int wm   = warp >> 1;
    const int wn   = (warp & 1) * 32;
    const int gq   = lane >> 2;
    const int tg   = lane & 3;

    const float* inp = in + (size_t)n * CIN * 1024;

    float acc[2][4][4];
#pragma unroll
    for (int mt = 0; mt < 2; mt++)
#pragma unroll
        for (int nt = 0; nt < 4; nt++)
#pragma unroll
            for (int i = 0; i < 4; i++) acc[mt][nt][i] = 0.f;

    const int NCH = CIN / 8;
    for (int ch = 0; ch < NCH; ch++) {
        const int ci0 = ch * 8;

        for (int idx = tid; idx < A_PLANE; idx += 256) {
            int ci  = idx / 216;
            int rem = idx - ci * 216;
            int r   = rem / 36;
            int c   = rem - r * 36;
            int ih  = r0g - 1 + r;
            int iw  = c - 1;
            float v = 0.f;
            if (c < 34 && (unsigned)ih < 32u && (unsigned)iw < 32u)
                v = inp[(size_t)(ci0 + ci) * 1024 + ih * 32 + iw];
            if (PRE) v = fmaxf(v, 0.f);
            float hi = tf32_rna(v);
            sAh[idx] = hi;
            sAl[idx] = tf32_rna(v - hi);
        }

        for (int idx = tid; idx < 1152; idx += 256) {
            int row = idx >> 4;
            int c4  = idx & 15;
            int tap = row >> 3;
            int ci  = row & 7;
            size_t g = (size_t)(tap * CIN + ci0 + ci) * COUT + oc0 + 4 * c4;
            int s = row * 72 + 4 * c4;
            *reinterpret_cast<float4*>(sBh + s) =
                *reinterpret_cast<const float4*>(wh + g);
            *reinterpret_cast<float4*>(sBl + s) =
                *reinterpret_cast<const float4*>(wl + g);
        }
        __syncthreads();

#pragma unroll
        for (int kh = 0; kh < 3; kh++)
#pragma unroll
            for (int kw = 0; kw < 3; kw++) {
                const int tap = kh * 3 + kw;
                unsigned bh[8], bl[8];
                const int bbase = (tap * 8 + tg) * 72 + wn + gq;
#pragma unroll
                for (int nt = 0; nt < 4; nt++) {
                    bh[2*nt]   = __float_as_uint(sBh[bbase + 8 * nt]);
                    bh[2*nt+1] = __float_as_uint(sBh[bbase + 288 + 8 * nt]);
                    bl[2*nt]   = __float_as_uint(sBl[bbase + 8 * nt]);
                    bl[2*nt+1] = __float_as_uint(sBl[bbase + 288 + 8 * nt]);
                }
#pragma unroll
                for (int mt = 0; mt < 2; mt++) {
                    const int ab = tg * 216 + (wm + kh) * 36 + mt * 16 + gq + kw;
                    unsigned ah[4], al[4];
                    ah[0] = __float_as_uint(sAh[ab]);
                    ah[1] = __float_as_uint(sAh[ab + 8]);
                    ah[2] = __float_as_uint(sAh[ab + 864]);
                    ah[3] = __float_as_uint(sAh[ab + 872]);
                    al[0] = __float_as_uint(sAl[ab]);
                    al[1] = __float_as_uint(sAl[ab + 8]);
                    al[2] = __float_as_uint(sAl[ab + 864]);
                    al[3] = __float_as_uint(sAl[ab + 872]);
#pragma unroll
                    for (int nt = 0; nt < 4; nt++) mma_tf32(acc[mt][nt], ah, bh + 2*nt);
#pragma unroll
                    for (int nt = 0; nt < 4; nt++) mma_tf32(acc[mt][nt], ah, bl + 2*nt);
#pragma unroll
                    for (int nt = 0; nt < 4; nt++) mma_tf32(acc[mt][nt], al, bh + 2*nt);
                }
            }
        __syncthreads();
    }

    const int gr = r0g + wm;
#pragma unroll
    for (int mt = 0; mt < 2; mt++) {
        const int cb = mt * 16 + gq;
#pragma unroll
        for (int nt = 0; nt < 4; nt++) {
            const int ocb = oc0 + wn + nt * 8 + 2 * tg;
            float bv0 = BIAS ? bias[ocb]     : 0.f;
            float bv1 = BIAS ? bias[ocb + 1] : 0.f;
            float d0 = acc[mt][nt][0] + bv0;
            float d1 = acc[mt][nt][1] + bv1;
            float d2 = acc[mt][nt][2] + bv0;
            float d3 = acc[mt][nt][3] + bv1;
            if (POST) {
                d0 = fmaxf(d0, 0.f); d1 = fmaxf(d1, 0.f);
                d2 = fmaxf(d2, 0.f); d3 = fmaxf(d3, 0.f);
            }
            float* o0 = out + ((size_t)(n * COUT + ocb)) * 1024 + gr * 32;
            float* o1 = o0 + 1024;
            o0[cb]     = d0;
            o1[cb]     = d1;
            o0[cb + 8] = d2;
            o1[cb + 8] = d3;
        }
    }
}

// ---------------------------------------------------------------------------
// 4x4 stride-2 pad-1 conv (HIN=64 -> HOUT=32) via split-TF32 mma.
// grid(COUT/64, 8, B), block 256. A tile split by input-col parity:
// half h: iw = 2j-1+h. Layout [h][8ci][10r][36c] (plane 360 -> conflict-free).
// Taps staged in 2 groups of 8 (B group = 64 rows x 72).
// ---------------------------------------------------------------------------
#define A4_HALF  2880
#define A4_PLANE (2*A4_HALF)           // 5760
#define B4_PLANE (64*72)               // 4608
#define SM4_BYTES ((2*A4_PLANE + 2*B4_PLANE) * 4)   // 82944

template<int CIN, int COUT, bool POST>
__global__ void __launch_bounds__(256, 2) conv4x4s2_mma_k(
    const float* __restrict__ in, const float* __restrict__ wh,
    const float* __restrict__ wl, const float* __restrict__ bias,
    float* __restrict__ out)
{
    extern __shared__ float smx[];
    float* sAh = smx;
    float* sAl = smx + A4_PLANE;
    float* sBh = smx + 2 * A4_PLANE;
    float* sBl = smx + 2 * A4_PLANE + B4_PLANE;

    const int n    = blockIdx.z;
    const int oc0  = blockIdx.x * 64;
    const int r0   = blockIdx.y * 4;     // output rows (of 32)
    const int tid  = threadIdx.x;
    const int warp = tid >> 5;
    const int lane = tid & 31;
    const int wm   = warp >> 1;
    const int wn   = (warp & 1) * 32;
    const int gq   = lane >> 2;
    const int tg   = lane & 3;

    const float* inp = in + (size_t)n * CIN * 4096;

    float acc[2][4][4];
#pragma unroll
    for (int mt = 0; mt < 2; mt++)
#pragma unroll
        for (int nt = 0; nt < 4; nt++)
#pragma unroll
            for (int i = 0; i < 4; i++) acc[mt][nt][i] = 0.f;

    const int NCH = CIN / 8;
    for (int ch = 0; ch < NCH; ch++) {
        const int ci0 = ch * 8;

        // stage A (both parity halves)
        for (int idx = tid; idx < A4_PLANE; idx += 256) {
            int h   = idx / A4_HALF;
            int rem = idx - h * A4_HALF;
            int ci  = rem / 360;
            int r2  = rem - ci * 360;
            int r   = r2 / 36;
            int j   = r2 - r * 36;
            int ih  = 2 * r0 - 1 + r;
            int iw  = 2 * j - 1 + h;
            float v = 0.f;
            if ((unsigned)ih < 64u && (unsigned)iw < 64u)
                v = inp[(size_t)(ci0 + ci) * 4096 + ih * 64 + iw];
            float hi = tf32_rna(v);
            sAh[idx] = hi;
            sAl[idx] = tf32_rna(v - hi);
        }

#pragma unroll
        for (int ggrp = 0; ggrp < 2; ggrp++) {
            // stage B group (taps ggrp*8 .. ggrp*8+7)
            for (int idx = tid; idx < 1024; idx += 256) {
                int row = idx >> 4;
                int c4  = idx & 15;
                int tap = ggrp * 8 + (row >> 3);
                int ci  = row & 7;
                size_t g = (size_t)(tap * CIN + ci0 + ci) * COUT + oc0 + 4 * c4;
                int s = row * 72 + 4 * c4;
                *reinterpret_cast<float4*>(sBh + s) =
                    *reinterpret_cast<const float4*>(wh + g);
                *reinterpret_cast<float4*>(sBl + s) =
                    *reinterpret_cast<const float4*>(wl + g);
            }
            __syncthreads();

#pragma unroll
            for (int tl = 0; tl < 8; tl++) {
                const int t  = ggrp * 8 + tl;
                const int kh = t >> 2;
                const int kw = t & 3;
                const int h  = kw & 1;          // kw odd -> even iw half
                const int joff = kw >> 1;
                unsigned bh[8], bl[8];
                const int bbase = (tl * 8 + tg) * 72 + wn + gq;
#pragma unroll
                for (int nt = 0; nt < 4; nt++) {
                    bh[2*nt]   = __float_as_uint(sBh[bbase + 8 * nt]);
                    bh[2*nt+1] = __float_as_uint(sBh[bbase + 288 + 8 * nt]);
                    bl[2*nt]   = __float_as_uint(sBl[bbase + 8 * nt]);
                    bl[2*nt+1] = __float_as_uint(sBl[bbase + 288 + 8 * nt]);
                }
#pragma unroll
                for (int mt = 0; mt < 2; mt++) {
                    const int ab = h * A4_HALF + tg * 360 + (2 * wm + kh) * 36
                                   + mt * 16 + gq + joff;
                    unsigned ah[4], al[4];
                    ah[0] = __float_as_uint(sAh[ab]);
                    ah[1] = __float_as_uint(sAh[ab + 8]);
                    ah[2] = __float_as_uint(sAh[ab + 1440]);
                    ah[3] = __float_as_uint(sAh[ab + 1448]);
                    al[0] = __float_as_uint(sAl[ab]);
                    al[1] = __float_as_uint(sAl[ab + 8]);
                    al[2] = __float_as_uint(sAl[ab + 1440]);
                    al[3] = __float_as_uint(sAl[ab + 1448]);
#pragma unroll
                    for (int nt = 0; nt < 4; nt++) mma_tf32(acc[mt][nt], ah, bh + 2*nt);
#pragma unroll
                    for (int nt = 0; nt < 4; nt++) mma_tf32(acc[mt][nt], ah, bl + 2*nt);
#pragma unroll
                    for (int nt = 0; nt < 4; nt++) mma_tf32(acc[mt][nt], al, bh + 2*nt);
                }
            }
            __syncthreads();
        }
    }

    const int gr = r0 + wm;
#pragma unroll
    for (int mt = 0; mt < 2; mt++) {
        const int cb = mt * 16 + gq;
#pragma unroll
        for (int nt = 0; nt < 4; nt++) {
            const int ocb = oc0 + wn + nt * 8 + 2 * tg;
            float bv0 = bias[ocb];
            float bv1 = bias[ocb + 1];
            float d0 = acc[mt][nt][0] + bv0;
            float d1 = acc[mt][nt][1] + bv1;
            float d2 = acc[mt][nt][2] + bv0;
            float d3 = acc[mt][nt][3] + bv1;
            if (POST) {
                d0 = fmaxf(d0, 0.f); d1 = fmaxf(d1, 0.f);
                d2 = fmaxf(d2, 0.f); d3 = fmaxf(d3, 0.f);
            }
            float* o0 = out + ((size_t)(n * COUT + ocb)) * 1024 + gr * 32;
            float* o1 = o0 + 1024;
            o0[cb]     = d0;
            o1[cb]     = d1;
            o0[cb + 8] = d2;
            o1[cb + 8] = d3;
        }
    }
}

// ---------------------------------------------------------------------------
// ConvTranspose 4x4 s2 p1 (32x32 -> 64x64) via split-TF32 mma.
// Parity decomposition: class (po,pw) is a 2x2-tap stride-1 conv.
// grid(COUT/64, 32 = 8 rowtiles x 4 classes, B), block 256.
// A layout identical to conv3x3 ([8ci][6r][36c]); B = 32 rows x 72.
// ---------------------------------------------------------------------------
#define BT_PLANE (32*72)               // 2304
#define SMT_BYTES ((2*A_PLANE + 2*BT_PLANE) * 4)   // 32256

template<int CIN, int COUT, bool PRE, bool POST>
__global__ void __launch_bounds__(256, 2) convT_mma_k(
    const float* __restrict__ in, const float* __restrict__ wh,
    const float* __restrict__ wl, const float* __restrict__ bias,
    float* __restrict__ out)
{
    extern __shared__ float smx[];
    float* sAh = smx;
    float* sAl = smx + A_PLANE;
    float* sBh = smx + 2 * A_PLANE;
    float* sBl = smx + 2 * A_PLANE + BT_PLANE;

    const int n    = blockIdx.z;
    const int oc0  = blockIdx.x * 64;
    const int cls  = blockIdx.y & 3;
    const int r0   = (blockIdx.y >> 2) * 4;   // oh' base (of 32)
    const int po   = cls >> 1;
    const int pw   = cls & 1;
    const int tid  = threadIdx.x;
    const int warp = tid >> 5;
    const int lane = tid & 31;
    const int wm   = warp >> 1;
    const int wn   = (warp & 1) * 32;
    const int gq   = lane >> 2;
    const int tg   = lane & 3;

    const float* inp = in + (size_t)n * CIN * 1024;

    float acc[2][4][4];
#pragma unroll
    for (int mt = 0; mt < 2; mt++)
#pragma unroll
        for (int nt = 0; nt < 4; nt++)
#pragma unroll
            for (int i = 0; i < 4; i++) acc[mt][nt][i] = 0.f;

    const int NCH = CIN / 8;
    for (int ch = 0; ch < NCH; ch++) {
        const int ci0 = ch * 8;

        for (int idx = tid; idx < A_PLANE; idx += 256) {
            int ci  = idx / 216;
            int rem = idx - ci * 216;
            int r   = rem / 36;
            int c   = rem - r * 36;
            int ih  = r0 - 1 + r;
            int iw  = c - 1;
            float v = 0.f;
            if (c < 34 && (unsigned)ih < 32u && (unsigned)iw < 32u)
                v = inp[(size_t)(ci0 + ci) * 1024 + ih * 32 + iw];
            if (PRE) v = fmaxf(v, 0.f);
            float hi = tf32_rna(v);
            sAh[idx] = hi;
            sAl[idx] = tf32_rna(v - hi);
        }

        for (int idx = tid; idx < 512; idx += 256) {
            int row = idx >> 4;
            int c4  = idx & 15;
            int tap = row >> 3;
            int ci  = row & 7;
            size_t g = (size_t)((cls * 4 + tap) * CIN + ci0 + ci) * COUT + oc0 + 4 * c4;
            int s = row * 72 + 4 * c4;
            *reinterpret_cast<float4*>(sBh + s) =
                *reinterpret_cast<const float4*>(wh + g);
            *reinterpret_cast<float4*>(sBl + s) =
                *reinterpret_cast<const float4*>(wl + g);
        }
        __syncthreads();

#pragma unroll
        for (int tap = 0; tap < 4; tap++) {
            const int khi = tap >> 1, kwi = tap & 1;
            const int rloc = wm + 1 + (po ? (1 - khi) : -khi);
            const int cloc = 1 + (pw ? (1 - kwi) : -kwi);
            unsigned bh[8], bl[8];
            const int bbase = (tap * 8 + tg) * 72 + wn + gq;
#pragma unroll
            for (int nt = 0; nt < 4; nt++) {
                bh[2*nt]   = __float_as_uint(sBh[bbase + 8 * nt]);
                bh[2*nt+1] = __float_as_uint(sBh[bbase + 288 + 8 * nt]);
                bl[2*nt]   = __float_as_uint(sBl[bbase + 8 * nt]);
                bl[2*nt+1] = __float_as_uint(sBl[bbase + 288 + 8 * nt]);
            }
#pragma unroll
            for (int mt = 0; mt < 2; mt++) {
                const int ab = tg * 216 + rloc * 36 + mt * 16 + gq + cloc;
                unsigned ah[4], al[4];
                ah[0] = __float_as_uint(sAh[ab]);
                ah[1] = __float_as_uint(sAh[ab + 8]);
                ah[2] = __float_as_uint(sAh[ab + 864]);
                ah[3] = __float_as_uint(sAh[ab + 872]);
                al[0] = __float_as_uint(sAl[ab]);
                al[1] = __float_as_uint(sAl[ab + 8]);
                al[2] = __float_as_uint(sAl[ab + 864]);
                al[3] = __float_as_uint(sAl[ab + 872]);
#pragma unroll
                for (int nt = 0; nt < 4; nt++) mma_tf32(acc[mt][nt], ah, bh + 2*nt);
#pragma unroll
                for (int nt = 0; nt < 4; nt++) mma_tf32(acc[mt][nt], ah, bl + 2*nt);
#pragma unroll
                for (int nt = 0; nt < 4; nt++) mma_tf32(acc[mt][nt], al, bh + 2*nt);
            }
        }
        __syncthreads();
    }

    const int gr = 2 * (r0 + wm) + po;          // output row (of 64)
#pragma unroll
    for (int mt = 0; mt < 2; mt++) {
        const int cb = mt * 16 + gq;
#pragma unroll
        for (int nt = 0; nt < 4; nt++) {
            const int ocb = oc0 + wn + nt * 8 + 2 * tg;
            float bv0 = bias[ocb];
            float bv1 = bias[ocb + 1];
            float d0 = acc[mt][nt][0] + bv0;
            float d1 = acc[mt][nt][1] + bv1;
            float d2 = acc[mt][nt][2] + bv0;
            float d3 = acc[mt][nt][3] + bv1;
            if (POST) {
                d0 = fmaxf(d0, 0.f); d1 = fmaxf(d1, 0.f);
                d2 = fmaxf(d2, 0.f); d3 = fmaxf(d3, 0.f);
            }
            float* o0 = out + ((size_t)(n * COUT + ocb)) * 4096 + gr * 64;
            float* o1 = o0 + 4096;
            o0[2 * cb + pw]      = d0;
            o1[2 * cb + pw]      = d1;
            o0[2 * cb + 16 + pw] = d2;
            o1[2 * cb + 16 + pw] = d3;
        }
    }
}

// ---------------------------------------------------------------------------
// 4x4 stride-2 pad-1 conv, f32x2 packed (enc1 only, CIN=3).
// ---------------------------------------------------------------------------
template<int CIN, int COUT, int HIN, int HOUT, bool POST>
__global__ void __launch_bounds__(128, 3) conv4x4s2_k(
    const float* __restrict__ in, const float* __restrict__ w,
    const float* __restrict__ bias, float* __restrict__ out)
{
    extern __shared__ char dsm[];
    ull*   s_w2  = (ull*)dsm;
    float* s_in0 = (float*)(dsm + (size_t)CIN * 4 * 16 * 8);
    float* s_in1 = s_in0 + 66 * 66;

    const int n   = blockIdx.z;
    const int oc0 = blockIdx.x * 4;
    const int TB  = HOUT / 32;
    const int r0  = (blockIdx.y / TB) * 32;
    const int c0  = (blockIdx.y % TB) * 32;
    const int tid = threadIdx.x;
    const int loh0 = (tid >> 3) * 2;
    const int low0 = (tid & 7) * 4;

    for (int i = tid; i < 4 * CIN * 16; i += 128) {
        int oc = i / (CIN * 16);
        int r  = i - oc * (CIN * 16);
        int ci = r / 16, kk = r - ci * 16;
        float v = w[(size_t)(oc0 + oc) * CIN * 16 + r];
        s_w2[(ci * 4 + oc) * 16 + kk] = pk2(v, v);
    }

    const int ihb = 2 * r0 - 1, iwb = 2 * c0 - 1;
    const float* inp = in + (size_t)n * CIN * HIN * HIN;

    for (int idx = tid; idx < 66 * 66; idx += 128) {
        int r = idx / 66, c = idx - r * 66;
        int ih = ihb + r, iw = iwb + c;
        float v = 0.f;
        if ((unsigned)ih < (unsigned)HIN && (unsigned)iw < (unsigned)HIN)
            v = inp[(size_t)ih * HIN + iw];
        s_in0[idx] = v;
    }
    __syncthreads();

    ull acc[4][4];
#pragma unroll
    for (int a = 0; a < 4; a++)
#pragma unroll
        for (int q = 0; q < 4; q++) acc[a][q] = 0ULL;

    for (int ci = 0; ci < CIN; ci++) {
        const float* cur = (ci & 1) ? s_in1 : s_in0;
        if (ci + 1 < CIN) {
            float* nb = ((ci + 1) & 1) ? s_in1 : s_in0;
            const float* inn = inp + (size_t)(ci + 1) * HIN * HIN;
            for (int idx = tid; idx < 66 * 66; idx += 128) {
                int r = idx / 66, c = idx - r * 66;
                int ih = ihb + r, iw = iwb + c;
                float v = 0.f;
                if ((unsigned)ih < (unsigned)HIN && (unsigned)iw < (unsigned)HIN)
                    v = inn[(size_t)ih * HIN + iw];
                nb[idx] = v;
            }
        }

        const int rowA0 = 2 * loh0;
        const int base  = 2 * low0;
        const ull* wci  = s_w2 + ci * 64;
#pragma unroll
        for (int kh = 0; kh < 4; kh++) {
            const float* pa = cur + (rowA0 + kh) * 66 + base;
            const float* pb = pa + 132;
            ull P[10];
#pragma unroll
            for (int c = 0; c < 10; c++) P[c] = pk2(pa[c], pb[c]);
#pragma unroll
            for (int oc = 0; oc < 4; oc++)
#pragma unroll
                for (int kw = 0; kw < 4; kw++) {
                    ull w2 = wci[oc * 16 + kh * 4 + kw];
#pragma unroll
                    for (int pw = 0; pw < 4; pw++)
                        fma2(acc[oc][pw], P[2 * pw + kw], w2);
                }
        }
        __syncthreads();
    }

#pragma unroll
    for (int oc = 0; oc < 4; oc++) {
        float bv = bias[oc0 + oc];
        float* obase = out + ((size_t)(n * COUT + oc0 + oc)) * HOUT * HOUT +
                       (size_t)(r0 + loh0) * HOUT + (c0 + low0);
#pragma unroll
        for (int pw = 0; pw < 4; pw++) {
            float2 v = unpk(acc[oc][pw]);
            v.x += bv; v.y += bv;
            if (POST) { v.x = fmaxf(v.x, 0.f); v.y = fmaxf(v.y, 0.f); }
            obase[pw]        = v.x;
            obase[HOUT + pw] = v.y;
        }
    }
}

// ---------------------------------------------------------------------------
// ConvTranspose2d k=4 s=2 p=1, f32x2 packed (tc2 only).
// ---------------------------------------------------------------------------
template<int CIN, int COUT, int OCB, int HIN, int HOUT, bool PRE, bool POST>
__global__ void __launch_bounds__(128, 4) convT4x4s2_k(
    const float* __restrict__ in, const float* __restrict__ w,
    const float* __restrict__ bias, float* __restrict__ out)
{
    const int n   = blockIdx.z;
    const int oc0 = blockIdx.x * OCB;
    const int TB  = HOUT / 32;
    const int r0  = (blockIdx.y / TB) * 32;
    const int c0  = (blockIdx.y % TB) * 32;
    const int tid = threadIdx.x;
    const int loh0 = (tid >> 3) * 2;
    const int low0 = (tid & 7) * 4;

    __shared__ float s_in[2][18 * 18];
    __shared__ ull   s_w2[CIN * OCB * 8];

    for (int i = tid; i < CIN * OCB * 8; i += 128) {
        int per = OCB * 8;
        int ci = i / per;
        int r  = i - ci * per;
        int oc = r >> 3;
        int t  = r & 7;
        int kw = t >> 1, p = t & 1;
        const float* wb = w + ((size_t)ci * COUT + oc0 + oc) * 16;
        s_w2[i] = pk2(wb[(p * 2 + 1) * 4 + kw], wb[(p * 2) * 4 + kw]);
    }

    const int ihb = (r0 - 2) / 2;
    const int iwb = (c0 - 2) / 2;
    const float* inp = in + (size_t)n * CIN * HIN * HIN;

    int goff[3];
#pragma unroll
    for (int s = 0; s < 3; s++) {
        int idx = tid + s * 128;
        int r = idx / 18, c = idx - r * 18;
        int ih = ihb + r, iw = iwb + c;
        goff[s] = ((unsigned)ih < (unsigned)HIN && (unsigned)iw < (unsigned)HIN)
                      ? ih * HIN + iw : -1;
    }

    {
        float* b0 = s_in[0];
#pragma unroll
        for (int s = 0; s < 2; s++) {
            float v = (goff[s] >= 0) ? inp[goff[s]] : 0.f;
            if (PRE) v = fmaxf(v, 0.f);
            b0[tid + s * 128] = v;
        }
        if (tid < 68) {
            float v = (goff[2] >= 0) ? inp[goff[2]] : 0.f;
            if (PRE) v = fmaxf(v, 0.f);
            b0[tid + 256] = v;
        }
    }
    __syncthreads();

    ull acc[OCB][4];
#pragma unroll
    for (int a = 0; a < OCB; a++)
#pragma unroll
        for (int q = 0; q < 4; q++) acc[a][q] = 0ULL;

    const int rb = loh0 >> 1;
    const int cb = low0 >> 1;

    for (int ci = 0; ci < CIN; ci++) {
        const float* cur = s_in[ci & 1];
        if (ci + 1 < CIN) {
            const float* inn = inp + (size_t)(ci + 1) * HIN * HIN;
            float* nb = s_in[(ci + 1) & 1];
#pragma unroll
            for (int s = 0; s < 2; s++) {
                float v = (goff[s] >= 0) ? inn[goff[s]] : 0.f;
                if (PRE) v = fmaxf(v, 0.f);
                nb[tid + s * 128] = v;
            }
            if (tid < 68) {
                float v = (goff[2] >= 0) ? inn[goff[2]] : 0.f;
                if (PRE) v = fmaxf(v, 0.f);
                nb[tid + 256] = v;
            }
        }

        ull A[4], B[4];
#pragma unroll
        for (int c = 0; c < 4; c++) {
            float x0 = cur[rb * 18 + cb + c];
            float x1 = cur[(rb + 1) * 18 + cb + c];
            float x2 = cur[(rb + 2) * 18 + cb + c];
            A[c] = pk2(x1, x2);
            B[c] = pk2(x0, x1);
        }

        const ull* wci = s_w2 + ci * OCB * 8;
#pragma unroll
        for (int oc = 0; oc < OCB; oc++) {
            const ull* wp = wci + oc * 8;
#pragma unroll
            for (int pw = 0; pw < 4; pw++) {
                const int kwh = (pw & 1) ? 0 : 1;
                const int rh  = (pw >> 1) + 1 + (pw & 1);
                fma2(acc[oc][pw], A[rh],     wp[kwh * 2 + 0]);
                fma2(acc[oc][pw], B[rh],     wp[kwh * 2 + 1]);
                fma2(acc[oc][pw], A[rh - 1], wp[(kwh + 2) * 2 + 0]);
                fma2(acc[oc][pw], B[rh - 1], wp[(kwh + 2) * 2 + 1]);
            }
        }
        __syncthreads();
    }

#pragma unroll
    for (int oc = 0; oc < OCB; oc++) {
        float bv = bias[oc0 + oc];
        float* obase = out + ((size_t)(n * COUT + oc0 + oc)) * HOUT * HOUT +
                       (size_t)(r0 + loh0) * HOUT + (c0 + low0);
#pragma unroll
        for (int pw = 0; pw < 4; pw++) {
            float2 v = unpk(acc[oc][pw]);
            v.x += bv; v.y += bv;
            if (POST) { v.x = fmaxf(v.x, 0.f); v.y = fmaxf(v.y, 0.f); }
            obase[pw]        = v.x;
            obase[HOUT + pw] = v.y;
        }
    }
}

// ---------------------------------------------------------------------------
// 1x1 conv on 32x32 images.
// ---------------------------------------------------------------------------
template<int CIN, int COUT, bool PRE, bool BIAS, bool ADDRES>
__global__ void __launch_bounds__(256) conv1x1_k(
    const float* __restrict__ in, const float* __restrict__ w,
    const float* __restrict__ bias, float* __restrict__ out)
{
    const int n   = blockIdx.y;
    const int oc0 = blockIdx.x * 4;
    const int tid = threadIdx.x;
    const int hw0 = tid * 4;

    __shared__ float s_w[4 * CIN];
    for (int i = tid; i < 4 * CIN; i += 256)
        s_w[i] = w[(oc0 + i / CIN) * CIN + (i % CIN)];
    __syncthreads();

    float acc[4][4];
#pragma unroll
    for (int a = 0; a < 4; a++)
#pragma unroll
        for (int q = 0; q < 4; q++) acc[a][q] = 0.f;

    const float* inp = in + (size_t)n * CIN * 1024 + hw0;
    for (int ci = 0; ci < CIN; ci++) {
        float4 v = *reinterpret_cast<const float4*>(inp + (size_t)ci * 1024);
        if (PRE) {
            v.x = fmaxf(v.x, 0.f); v.y = fmaxf(v.y, 0.f);
            v.z = fmaxf(v.z, 0.f); v.w = fmaxf(v.w, 0.f);
        }
#pragma unroll
        for (int oc = 0; oc < 4; oc++) {
            float wv = s_w[oc * CIN + ci];
            acc[oc][0] = fmaf(v.x, wv, acc[oc][0]);
            acc[oc][1] = fmaf(v.y, wv, acc[oc][1]);
            acc[oc][2] = fmaf(v.z, wv, acc[oc][2]);
            acc[oc][3] = fmaf(v.w, wv, acc[oc][3]);
        }
    }

#pragma unroll
    for (int oc = 0; oc < 4; oc++) {
        float bv = BIAS ? bias[oc0 + oc] : 0.f;
        float* op = out + ((size_t)(n * COUT + oc0 + oc)) * 1024 + hw0;
        float4 o;
        o.x = acc[oc][0] + bv; o.y = acc[oc][1] + bv;
        o.z = acc[oc][2] + bv; o.w = acc[oc][3] + bv;
        if (ADDRES) {
            float4 r = *reinterpret_cast<const float4*>(op);
            o.x += r.x; o.y += r.y; o.z += r.z; o.w += r.w;
        }
        *reinterpret_cast<float4*>(op) = o;
    }
}

// ---------------------------------------------------------------------------
// Vector quantizer.
// ---------------------------------------------------------------------------
#define VQ_SMEM ((32768 + 512 + 512 + 256) * 4)

__global__ void __launch_bounds__(256) vq_k(
    const float* __restrict__ ze, const float* __restrict__ E,
    float* __restrict__ zq, int* __restrict__ hist, float* __restrict__ mse)
{
    extern __shared__ float sm[];
    float* sE   = sm;
    float* sEsq = sm + 32768;
    int*   sHist= (int*)(sm + 33280);
    float* sRed = sm + 33792;

    const int tid = threadIdx.x;
    for (int i = tid; i < VQ_K * VQ_D; i += 256) sE[i] = E[i];
    for (int i = tid; i < VQ_K; i += 256) sHist[i] = 0;
    __syncthreads();
    for (int i = tid; i < VQ_K; i += 256) {
        const float* e = &sE[i * VQ_D];
        float s = 0.f;
#pragma unroll 16
        for (int d = 0; d < VQ_D; d++) s = fmaf(e[d], e[d], s);
        sEsq[i] = s;
    }
    __syncthreads();

    const int p  = blockIdx.x * 256 + tid;
    const int n  = p >> 10;
    const int hw = p & 1023;
    const float* zp = ze + (size_t)n * VQ_D * 1024 + hw;

    float f[VQ_D];
#pragma unroll
    for (int d = 0; d < VQ_D; d++) f[d] = zp[(size_t)d * 1024];

    float best = 3.4e38f;
    int   bi   = 0;
    for (int k = 0; k < VQ_K; k++) {
        const float4* e4 = reinterpret_cast<const float4*>(&sE[k * VQ_D]);
        float s0 = 0.f, s1 = 0.f, s2 = 0.f, s3 = 0.f;
#pragma unroll
        for (int d = 0; d < VQ_D / 4; d++) {
            float4 e = e4[d];
            s0 = fmaf(e.x, f[4 * d + 0], s0);
            s1 = fmaf(e.y, f[4 * d + 1], s1);
            s2 = fmaf(e.z, f[4 * d + 2], s2);
            s3 = fmaf(e.w, f[4 * d + 3], s3);
        }
        float score = sEsq[k] - 2.f * ((s0 + s1) + (s2 + s3));
        if (score < best) { best = score; bi = k; }
    }

    const float* eb = &sE[bi * VQ_D];
    float* zqp = zq + (size_t)n * VQ_D * 1024 + hw;
    float md = 0.f;
#pragma unroll
    for (int d = 0; d < VQ_D; d++) {
        float ev = eb[d];
        float dd = f[d] - ev;
        md = fmaf(dd, dd, md);
        zqp[(size_t)d * 1024] = ev;
    }

    atomicAdd(&sHist[bi], 1);
    sRed[tid] = md;
    __syncthreads();
    for (int s = 128; s > 0; s >>= 1) {
        if (tid < s) sRed[tid] += sRed[tid + s];
        __syncthreads();
    }
    if (tid == 0) atomicAdd(mse, sRed[0]);
    for (int i = tid; i < VQ_K; i += 256) {
        int c = sHist[i];
        if (c) atomicAdd(&hist[i], c);
    }
}

__global__ void finalize_k(const int* __restrict__ hist,
                           const float* __restrict__ mse,
                           float* __restrict__ out)
{
    __shared__ float red[VQ_K];
    const int k = threadIdx.x;
    float pb = (float)hist[k] * (1.f / 65536.f);
    red[k] = pb * log2f(pb + 1e-10f);
    __syncthreads();
    for (int s = 256; s > 0; s >>= 1) {
        if (k < s) red[k] += red[k + s];
        __syncthreads();
    }
    if (k == 0) {
        float H = -red[0];
        float m = mse[0] * (1.f / (65536.f * 64.f));
        out[0]       = 1.25f * m;
        out[OUT_ELQ] = m;
        out[OUT_QLQ] = m;
        out[OUT_EW]  = exp2f(H);
    }
}

// ---------------------------------------------------------------------------
// Launch
// ---------------------------------------------------------------------------
extern "C" void kernel_launch(void* const* d_in, const int* in_sizes, int n_in,
                              void* d_out, int out_size)
{
    (void)in_sizes; (void)n_in; (void)out_size;
    const float* x          = (const float*)d_in[0];
    const float* enc_w1     = (const float*)d_in[1];
    const float* enc_b1     = (const float*)d_in[2];
    const float* enc_w2     = (const float*)d_in[3];
    const float* enc_b2     = (const float*)d_in[4];
    const float* enc_w3     = (const float*)d_in[5];
    const float* enc_b3     = (const float*)d_in[6];
    const float* enc_w4     = (const float*)d_in[7];
    const float* enc_b4     = (const float*)d_in[8];
    const float* enc_res_w1 = (const float*)d_in[9];
    const float* enc_res_w2 = (const float*)d_in[10];
    const float* enc_adj_w  = (const float*)d_in[11];
    const float* enc_adj_b  = (const float*)d_in[12];
    const float* E          = (const float*)d_in[13];
    const float* dec_adj_w  = (const float*)d_in[14];
    const float* dec_adj_b  = (const float*)d_in[15];
    const float* dec_res_w1 = (const float*)d_in[16];
    const float* dec_res_w2 = (const float*)d_in[17];
    const float* tc1_w      = (const float*)d_in[18];
    const float* tc1_b      = (const float*)d_in[19];
    const float* tc2_w      = (const float*)d_in[20];
    const float* tc2_b      = (const float*)d_in[21];
    float* out = (float*)d_out;

    float *h1, *a, *b, *mid, *ze, *zq, *mse, *wh, *wl; int* hist;
    cudaGetSymbolAddress((void**)&h1,  g_h1);
    cudaGetSymbolAddress((void**)&a,   g_a);
    cudaGetSymbolAddress((void**)&b,   g_b);
    cudaGetSymbolAddress((void**)&mid, g_mid);
    cudaGetSymbolAddress((void**)&ze,  g_ze);
    cudaGetSymbolAddress((void**)&zq,  g_zq);
    cudaGetSymbolAddress((void**)&wh,  g_wh);
    cudaGetSymbolAddress((void**)&wl,  g_wl);
    cudaGetSymbolAddress((void**)&mse, g_mse);
    cudaGetSymbolAddress((void**)&hist, g_hist);

    cudaFuncSetAttribute(vq_k, cudaFuncAttributeMaxDynamicSharedMemorySize, VQ_SMEM);

    const int SMEM_C1 = 3 * 4 * 16 * 8 + 2 * 66 * 66 * 4;   // 36384
    cudaFuncSetAttribute(conv4x4s2_k<3, 64, 128, 64, true>,
                         cudaFuncAttributeMaxDynamicSharedMemorySize, SMEM_C1);

    cudaFuncSetAttribute(conv3x3_mma_k<128, 128, false, true,  true>,
                         cudaFuncAttributeMaxDynamicSharedMemorySize, SM3_BYTES);
    cudaFuncSetAttribute(conv3x3_mma_k<128, 128, false, false, true>,
                         cudaFuncAttributeMaxDynamicSharedMemorySize, SM3_BYTES);
    cudaFuncSetAttribute(conv3x3_mma_k<128, 64, true, true, false>,
                         cudaFuncAttributeMaxDynamicSharedMemorySize, SM3_BYTES);
    cudaFuncSetAttribute(conv3x3_mma_k<64, 128, false, false, true>,
                         cudaFuncAttributeMaxDynamicSharedMemorySize, SM3_BYTES);
    cudaFuncSetAttribute(conv4x4s2_mma_k<64, 128, true>,
                         cudaFuncAttributeMaxDynamicSharedMemorySize, SM4_BYTES);
    cudaFuncSetAttribute(convT_mma_k<128, 64, true, true>,
                         cudaFuncAttributeMaxDynamicSharedMemorySize, SMT_BYTES);

    reset_k<<<1, 512>>>(hist, mse);

    // ---- Encoder ----
    conv4x4s2_k<3, 64, 128, 64, true><<<dim3(16, 4, BATCH), 128, SMEM_C1>>>(x, enc_w1, enc_b1, h1);

    wsplit4_k<<<288, 256>>>(enc_w2, 64, 128, wh, wl);
    conv4x4s2_mma_k<64, 128, true><<<dim3(2, 8, BATCH), 256, SM4_BYTES>>>(h1, wh, wl, enc_b2, a);

    wsplit_k<<<288, 256>>>(enc_w3, 128, 128, wh, wl);
    conv3x3_mma_k<128, 128, false, true,  true><<<dim3(2, 8, BATCH), 256, SM3_BYTES>>>(a, wh, wl, enc_b3, b);
    wsplit_k<<<288, 256>>>(enc_w4, 128, 128, wh, wl);
    conv3x3_mma_k<128, 128, false, false, true><<<dim3(2, 8, BATCH), 256, SM3_BYTES>>>(b, wh, wl, enc_b4, a);
    wsplit_k<<<288, 256>>>(enc_res_w1, 128, 64, wh, wl);
    conv3x3_mma_k<128, 64, true, true, false><<<dim3(1, 8, BATCH), 256, SM3_BYTES>>>(a, wh, wl, nullptr, mid);
    conv1x1_k<64, 128, false, false, true><<<dim3(32, BATCH), 256>>>(mid, enc_res_w2, nullptr, a);
    wsplit_k<<<288, 256>>>(enc_res_w1 + 64 * 128 * 9, 128, 64, wh, wl);
    conv3x3_mma_k<128, 64, true, true, false><<<dim3(1, 8, BATCH), 256, SM3_BYTES>>>(a, wh, wl, nullptr, mid);
    conv1x1_k<64, 128, false, false, true><<<dim3(32, BATCH), 256>>>(mid, enc_res_w2 + 128 * 64, nullptr, a);
    conv1x1_k<128, 64, true, true, false><<<dim3(16, BATCH), 256>>>(a, enc_adj_w, enc_adj_b, ze);

    // ---- Vector quantizer ----
    vq_k<<<256, 256, VQ_SMEM>>>(ze, E, zq, hist, mse);
    finalize_k<<<1, 512>>>(hist, mse, out);

    // ---- Decoder ----
    wsplit_k<<<288, 256>>>(dec_adj_w, 64, 128, wh, wl);
    conv3x3_mma_k<64, 128, false, false, true><<<dim3(2, 8, BATCH), 256, SM3_BYTES>>>(zq, wh, wl, dec_adj_b, a);
    wsplit_k<<<288, 256>>>(dec_res_w1, 128, 64, wh, wl);
    conv3x3_mma_k<128, 64, true, true, false><<<dim3(1, 8, BATCH), 256, SM3_BYTES>>>(a, wh, wl, nullptr, mid);
    conv1x1_k<64, 128, false, false, true><<<dim3(32, BATCH), 256>>>(mid, dec_res_w2, nullptr, a);
    wsplit_k<<<288, 256>>>(dec_res_w1 + 64 * 128 * 9, 128, 64, wh, wl);
    conv3x3_mma_k<128, 64, true, true, false><<<dim3(1, 8, BATCH), 256, SM3_BYTES>>>(a, wh, wl, nullptr, mid);
    conv1x1_k<64, 128, false, false, true><<<dim3(32, BATCH), 256>>>(mid, dec_res_w2 + 128 * 64, nullptr, a);

    wsplitT_k<<<288, 256>>>(tc1_w, 128, 64, wh, wl);
    convT_mma_k<128, 64, true, true><<<dim3(1, 32, BATCH), 256, SMT_BYTES>>>(a, wh, wl, tc1_b, h1);

    convT4x4s2_k<64, 3, 3, 64, 128, false, false><<<dim3(1, 16, BATCH), 128>>>(h1, tc2_w, tc2_b, out + OUT_RECON_OFF);
}

// round 12
// speedup vs baseline: 1.0001x; 1.0001x over previous
#include <cuda_runtime.h>
#include <math.h>
#include <stdint.h>

// ---------------------------------------------------------------------------
// VQ-VAE forward. 3x3 convs, enc2 (4x4 s2), tc1 (convT 4x4 s2) via
// split-precision TF32 mma.sync implicit GEMM; rest fp32 FFMA2.
// Output layout (float32, 3145732 elems):
//   [0] e_and_q  [1..3145728] x_recon  [3145729] e_latent  [3145730] q_latent
//   [3145731] est_words
// ---------------------------------------------------------------------------

#define BATCH 64
#define VQ_K 512
#define VQ_D 64
#define OUT_RECON_OFF 1
#define OUT_RECON_N   (64*3*128*128)
#define OUT_ELQ  (OUT_RECON_OFF + OUT_RECON_N)
#define OUT_QLQ  (OUT_ELQ + 1)
#define OUT_EW   (OUT_QLQ + 1)

typedef unsigned long long ull;

// ---- packed f32x2 helpers --------------------------------------------------
__device__ __forceinline__ ull pk2(float lo, float hi) {
    ull r; asm("mov.b64 %0, {%1, %2};" : "=l"(r) : "f"(lo), "f"(hi)); return r;
}
__device__ __forceinline__ float2 unpk(ull v) {
    float2 r; asm("mov.b64 {%0, %1}, %2;" : "=f"(r.x), "=f"(r.y) : "l"(v)); return r;
}
__device__ __forceinline__ void fma2(ull& d, ull a, ull b) {
    asm("fma.rn.f32x2 %0, %1, %2, %0;" : "+l"(d) : "l"(a), "l"(b));
}

// ---- tf32 helpers ----------------------------------------------------------
__device__ __forceinline__ float tf32_rna(float x) {
    unsigned u; asm("cvt.rna.tf32.f32 %0, %1;" : "=r"(u) : "f"(x));
    return __uint_as_float(u);
}
__device__ __forceinline__ void mma_tf32(float* d, const unsigned* a, const unsigned* b) {
    asm volatile(
        "mma.sync.aligned.m16n8k8.row.col.f32.tf32.tf32.f32 "
        "{%0,%1,%2,%3}, {%4,%5,%6,%7}, {%8,%9}, {%0,%1,%2,%3};\n"
        : "+f"(d[0]), "+f"(d[1]), "+f"(d[2]), "+f"(d[3])
        : "r"(a[0]), "r"(a[1]), "r"(a[2]), "r"(a[3]), "r"(b[0]), "r"(b[1]));
}

// ---------------- scratch buffers -------------------------------------------
__device__ float g_h1 [64*64*64*64];
__device__ float g_a  [64*128*32*32];
__device__ float g_b  [64*128*32*32];
__device__ float g_mid[64*64*32*32];
__device__ float g_ze [64*64*32*32];
__device__ float g_zq [64*64*32*32];
__device__ float g_wh [128*128*9];     // split weights (hi)
__device__ float g_wl [128*128*9];     // split weights (lo)
__device__ int   g_hist[VQ_K];
__device__ float g_mse[1];

__global__ void reset_k(int* hist, float* mse) {
    int t = threadIdx.x;
    if (t < VQ_K) hist[t] = 0;
    if (t == 0)   mse[0] = 0.f;
}

// ---------------------------------------------------------------------------
// Weight pre-splits.
// ---------------------------------------------------------------------------
// 3x3 conv, OIHW -> [tap*CIN+ci][oc]
__global__ void wsplit_k(const float* __restrict__ w, int CIN, int COUT,
                         float* __restrict__ wh, float* __restrict__ wl)
{
    int total = COUT * CIN * 9;
    for (int j = blockIdx.x * blockDim.x + threadIdx.x; j < total;
         j += gridDim.x * blockDim.x) {
        int row = j / COUT;
        int oc  = j - row * COUT;
        int tap = row / CIN;
        int ci  = row - tap * CIN;
        float v = w[((size_t)oc * CIN + ci) * 9 + tap];
        float hi = tf32_rna(v);
        wh[j] = hi;
        wl[j] = tf32_rna(v - hi);
    }
}

// 4x4 conv, OIHW -> [tap*CIN+ci][oc], tap = kh*4+kw
__global__ void wsplit4_k(const float* __restrict__ w, int CIN, int COUT,
                          float* __restrict__ wh, float* __restrict__ wl)
{
    int total = COUT * CIN * 16;
    for (int j = blockIdx.x * blockDim.x + threadIdx.x; j < total;
         j += gridDim.x * blockDim.x) {
        int row = j / COUT;
        int oc  = j - row * COUT;
        int tap = row / CIN;
        int ci  = row - tap * CIN;
        float v = w[((size_t)oc * CIN + ci) * 16 + tap];
        float hi = tf32_rna(v);
        wh[j] = hi;
        wl[j] = tf32_rna(v - hi);
    }
}

// convT 4x4, (CIN,COUT,kh,kw) -> [(class*4+tap)*CIN+ci][oc]
// class = po*2+pw (output parities), tap = khi*2+kwi,
// kh = ((po+1)&1)+2*khi, kw = ((pw+1)&1)+2*kwi
__global__ void wsplitT_k(const float* __restrict__ w, int CIN, int COUT,
                          float* __restrict__ wh, float* __restrict__ wl)
{
    int total = 16 * CIN * COUT;
    for (int j = blockIdx.x * blockDim.x + threadIdx.x; j < total;
         j += gridDim.x * blockDim.x) {
        int row = j / COUT;
        int oc  = j - row * COUT;
        int ct  = row / CIN;
        int ci  = row - ct * CIN;
        int cls = ct >> 2, tap = ct & 3;
        int po = cls >> 1, pw = cls & 1;
        int kh = ((po + 1) & 1) + 2 * (tap >> 1);
        int kw = ((pw + 1) & 1) + 2 * (tap & 1);
        float v = w[((size_t)ci * COUT + oc) * 16 + kh * 4 + kw];
        float hi = tf32_rna(v);
        wh[j] = hi;
        wl[j] = tf32_rna(v - hi);
    }
}

// ---------------------------------------------------------------------------
// 3x3 stride-1 pad-1 conv on 32x32 via split-TF32 mma (3xTF32).
// grid(COUT/64, 8, B), block 256. CTA tile M=128 (4 rows x 32), N=64.
// smem: A hi/lo [8ci][6r][36c]; B hi/lo [72][72].
// ---------------------------------------------------------------------------
#define A_PLANE 1728
#define B_PLANE 5184
#define SM3_BYTES ((2*A_PLANE + 2*B_PLANE) * 4)    // 55296

template<int CIN, int COUT, bool PRE, bool POST, bool BIAS>
__global__ void __launch_bounds__(256, 2) conv3x3_mma_k(
    const float* __restrict__ in, const float* __restrict__ wh,
    const float* __restrict__ wl, const float* __restrict__ bias,
    float* __restrict__ out)
{
    extern __shared__ float smx[];
    float* sAh = smx;
    float* sAl = smx + A_PLANE;
    float* sBh = smx + 2 * A_PLANE;
    float* sBl = smx + 2 * A_PLANE + B_PLANE;

    const int n    = blockIdx.z;
    const int oc0  = blockIdx.x * 64;
    const int r0g  = blockIdx.y * 4;
    const int tid  = threadIdx.x;
    const int warp = tid >> 5;
    const int lane = tid & 31;
    const int wm   = warp >> 1;
    const int wn   = (warp & 1) * 32;
    const int gq   = lane >> 2;
    const int tg   = lane & 3;

    const float* inp = in + (size_t)n * CIN * 1024;

    float acc[2][4][4];
#pragma unroll
    for (int mt = 0; mt < 2; mt++)
#pragma unroll
        for (int nt = 0; nt < 4; nt++)
#pragma unroll
            for (int i = 0; i < 4; i++) acc[mt][nt][i] = 0.f;

    const int NCH = CIN / 8;
    for (int ch = 0; ch < NCH; ch++) {
        const int ci0 = ch * 8;

        for (int idx = tid; idx < A_PLANE; idx += 256) {
            int ci  = idx / 216;
            int rem = idx - ci * 216;
            int r   = rem / 36;
            int c   = rem - r * 36;
            int ih  = r0g - 1 + r;
            int iw  = c - 1;
            float v = 0.f;
            if (c < 34 && (unsigned)ih < 32u && (unsigned)iw < 32u)
                v = inp[(size_t)(ci0 + ci) * 1024 + ih * 32 + iw];
            if (PRE) v = fmaxf(v, 0.f);
            float hi = tf32_rna(v);
            sAh[idx] = hi;
            sAl[idx] = tf32_rna(v - hi);
        }

        for (int idx = tid; idx < 1152; idx += 256) {
            int row = idx >> 4;
            int c4  = idx & 15;
            int tap = row >> 3;
            int ci  = row & 7;
            size_t g = (size_t)(tap * CIN + ci0 + ci) * COUT + oc0 + 4 * c4;
            int s = row * 72 + 4 * c4;
            *reinterpret_cast<float4*>(sBh + s) =
                *reinterpret_cast<const float4*>(wh + g);
            *reinterpret_cast<float4*>(sBl + s) =
                *reinterpret_cast<const float4*>(wl + g);
        }
        __syncthreads();

#pragma unroll
        for (int kh = 0; kh < 3; kh++)
#pragma unroll
            for (int kw = 0; kw < 3; kw++) {
                const int tap = kh * 3 + kw;
                unsigned bh[8], bl[8];
                const int bbase = (tap * 8 + tg) * 72 + wn + gq;
#pragma unroll
                for (int nt = 0; nt < 4; nt++) {
                    bh[2*nt]   = __float_as_uint(sBh[bbase + 8 * nt]);
                    bh[2*nt+1] = __float_as_uint(sBh[bbase + 288 + 8 * nt]);
                    bl[2*nt]   = __float_as_uint(sBl[bbase + 8 * nt]);
                    bl[2*nt+1] = __float_as_uint(sBl[bbase + 288 + 8 * nt]);
                }
#pragma unroll
                for (int mt = 0; mt < 2; mt++) {
                    const int ab = tg * 216 + (wm + kh) * 36 + mt * 16 + gq + kw;
                    unsigned ah[4], al[4];
                    ah[0] = __float_as_uint(sAh[ab]);
                    ah[1] = __float_as_uint(sAh[ab + 8]);
                    ah[2] = __float_as_uint(sAh[ab + 864]);
                    ah[3] = __float_as_uint(sAh[ab + 872]);
                    al[0] = __float_as_uint(sAl[ab]);
                    al[1] = __float_as_uint(sAl[ab + 8]);
                    al[2] = __float_as_uint(sAl[ab + 864]);
                    al[3] = __float_as_uint(sAl[ab + 872]);
#pragma unroll
                    for (int nt = 0; nt < 4; nt++) mma_tf32(acc[mt][nt], ah, bh + 2*nt);
#pragma unroll
                    for (int nt = 0; nt < 4; nt++) mma_tf32(acc[mt][nt], ah, bl + 2*nt);
#pragma unroll
                    for (int nt = 0; nt < 4; nt++) mma_tf32(acc[mt][nt], al, bh + 2*nt);
                }
            }
        __syncthreads();
    }

    const int gr = r0g + wm;
#pragma unroll
    for (int mt = 0; mt < 2; mt++) {
        const int cb = mt * 16 + gq;
#pragma unroll
        for (int nt = 0; nt < 4; nt++) {
            const int ocb = oc0 + wn + nt * 8 + 2 * tg;
            float bv0 = BIAS ? bias[ocb]     : 0.f;
            float bv1 = BIAS ? bias[ocb + 1] : 0.f;
            float d0 = acc[mt][nt][0] + bv0;
            float d1 = acc[mt][nt][1] + bv1;
            float d2 = acc[mt][nt][2] + bv0;
            float d3 = acc[mt][nt][3] + bv1;
            if (POST) {
                d0 = fmaxf(d0, 0.f); d1 = fmaxf(d1, 0.f);
                d2 = fmaxf(d2, 0.f); d3 = fmaxf(d3, 0.f);
            }
            float* o0 = out + ((size_t)(n * COUT + ocb)) * 1024 + gr * 32;
            float* o1 = o0 + 1024;
            o0[cb]     = d0;
            o1[cb]     = d1;
            o0[cb + 8] = d2;
            o1[cb + 8] = d3;
        }
    }
}

// ---------------------------------------------------------------------------
// 4x4 stride-2 pad-1 conv (HIN=64 -> HOUT=32) via split-TF32 mma.
// grid(COUT/64, 8, B), block 256. A tile split by input-col parity:
// half h: iw = 2j-1+h. Layout [h][8ci][10r][36c] (plane 360 -> conflict-free).
// Taps staged in 2 groups of 8 (B group = 64 rows x 72).
// ---------------------------------------------------------------------------
#define A4_HALF  2880
#define A4_PLANE (2*A4_HALF)           // 5760
#define B4_PLANE (64*72)               // 4608
#define SM4_BYTES ((2*A4_PLANE + 2*B4_PLANE) * 4)   // 82944

template<int CIN, int COUT, bool POST>
__global__ void __launch_bounds__(256, 2) conv4x4s2_mma_k(
    const float* __restrict__ in, const float* __restrict__ wh,
    const float* __restrict__ wl, const float* __restrict__ bias,
    float* __restrict__ out)
{
    extern __shared__ float smx[];
    float* sAh = smx;
    float* sAl = smx + A4_PLANE;
    float* sBh = smx + 2 * A4_PLANE;
    float* sBl = smx + 2 * A4_PLANE + B4_PLANE;

    const int n    = blockIdx.z;
    const int oc0  = blockIdx.x * 64;
    const int r0   = blockIdx.y * 4;     // output rows (of 32)
    const int tid  = threadIdx.x;
    const int warp = tid >> 5;
    const int lane = tid & 31;
    const int wm   = warp >> 1;
    const int wn   = (warp & 1) * 32;
    const int gq   = lane >> 2;
    const int tg   = lane & 3;

    const float* inp = in + (size_t)n * CIN * 4096;

    float acc[2][4][4];
#pragma unroll
    for (int mt = 0; mt < 2; mt++)
#pragma unroll
        for (int nt = 0; nt < 4; nt++)
#pragma unroll
            for (int i = 0; i < 4; i++) acc[mt][nt][i] = 0.f;

    const int NCH = CIN / 8;
    for (int ch = 0; ch < NCH; ch++) {
        const int ci0 = ch * 8;

        // stage A (both parity halves)
        for (int idx = tid; idx < A4_PLANE; idx += 256) {
            int h   = idx / A4_HALF;
            int rem = idx - h * A4_HALF;
            int ci  = rem / 360;
            int r2  = rem - ci * 360;
            int r   = r2 / 36;
            int j   = r2 - r * 36;
            int ih  = 2 * r0 - 1 + r;
            int iw  = 2 * j - 1 + h;
            float v = 0.f;
            if ((unsigned)ih < 64u && (unsigned)iw < 64u)
                v = inp[(size_t)(ci0 + ci) * 4096 + ih * 64 + iw];
            float hi = tf32_rna(v);
            sAh[idx] = hi;
            sAl[idx] = tf32_rna(v - hi);
        }

#pragma unroll
        for (int ggrp = 0; ggrp < 2; ggrp++) {
            // stage B group (taps ggrp*8 .. ggrp*8+7)
            for (int idx = tid; idx < 1024; idx += 256) {
                int row = idx >> 4;
                int c4  = idx & 15;
                int tap = ggrp * 8 + (row >> 3);
                int ci  = row & 7;
                size_t g = (size_t)(tap * CIN + ci0 + ci) * COUT + oc0 + 4 * c4;
                int s = row * 72 + 4 * c4;
                *reinterpret_cast<float4*>(sBh + s) =
                    *reinterpret_cast<const float4*>(wh + g);
                *reinterpret_cast<float4*>(sBl + s) =
                    *reinterpret_cast<const float4*>(wl + g);
            }
            __syncthreads();

#pragma unroll
            for (int tl = 0; tl < 8; tl++) {
                const int t  = ggrp * 8 + tl;
                const int kh = t >> 2;
                const int kw = t & 3;
                const int h  = kw & 1;          // kw odd -> even iw half
                const int joff = kw >> 1;
                unsigned bh[8], bl[8];
                const int bbase = (tl * 8 + tg) * 72 + wn + gq;
#pragma unroll
                for (int nt = 0; nt < 4; nt++) {
                    bh[2*nt]   = __float_as_uint(sBh[bbase + 8 * nt]);
                    bh[2*nt+1] = __float_as_uint(sBh[bbase + 288 + 8 * nt]);
                    bl[2*nt]   = __float_as_uint(sBl[bbase + 8 * nt]);
                    bl[2*nt+1] = __float_as_uint(sBl[bbase + 288 + 8 * nt]);
                }
#pragma unroll
                for (int mt = 0; mt < 2; mt++) {
                    const int ab = h * A4_HALF + tg * 360 + (2 * wm + kh) * 36
                                   + mt * 16 + gq + joff;
                    unsigned ah[4], al[4];
                    ah[0] = __float_as_uint(sAh[ab]);
                    ah[1] = __float_as_uint(sAh[ab + 8]);
                    ah[2] = __float_as_uint(sAh[ab + 1440]);
                    ah[3] = __float_as_uint(sAh[ab + 1448]);
                    al[0] = __float_as_uint(sAl[ab]);
                    al[1] = __float_as_uint(sAl[ab + 8]);
                    al[2] = __float_as_uint(sAl[ab + 1440]);
                    al[3] = __float_as_uint(sAl[ab + 1448]);
#pragma unroll
                    for (int nt = 0; nt < 4; nt++) mma_tf32(acc[mt][nt], ah, bh + 2*nt);
#pragma unroll
                    for (int nt = 0; nt < 4; nt++) mma_tf32(acc[mt][nt], ah, bl + 2*nt);
#pragma unroll
                    for (int nt = 0; nt < 4; nt++) mma_tf32(acc[mt][nt], al, bh + 2*nt);
                }
            }
            __syncthreads();
        }
    }

    const int gr = r0 + wm;
#pragma unroll
    for (int mt = 0; mt < 2; mt++) {
        const int cb = mt * 16 + gq;
#pragma unroll
        for (int nt = 0; nt < 4; nt++) {
            const int ocb = oc0 + wn + nt * 8 + 2 * tg;
            float bv0 = bias[ocb];
            float bv1 = bias[ocb + 1];
            float d0 = acc[mt][nt][0] + bv0;
            float d1 = acc[mt][nt][1] + bv1;
            float d2 = acc[mt][nt][2] + bv0;
            float d3 = acc[mt][nt][3] + bv1;
            if (POST) {
                d0 = fmaxf(d0, 0.f); d1 = fmaxf(d1, 0.f);
                d2 = fmaxf(d2, 0.f); d3 = fmaxf(d3, 0.f);
            }
            float* o0 = out + ((size_t)(n * COUT + ocb)) * 1024 + gr * 32;
            float* o1 = o0 + 1024;
            o0[cb]     = d0;
            o1[cb]     = d1;
            o0[cb + 8] = d2;
            o1[cb + 8] = d3;
        }
    }
}

// ---------------------------------------------------------------------------
// ConvTranspose 4x4 s2 p1 (32x32 -> 64x64) via split-TF32 mma.
// Parity decomposition: class (po,pw) is a 2x2-tap stride-1 conv.
// grid(COUT/64, 32 = 8 rowtiles x 4 classes, B), block 256.
// A layout identical to conv3x3 ([8ci][6r][36c]); B = 32 rows x 72.
// ---------------------------------------------------------------------------
#define BT_PLANE (32*72)               // 2304
#define SMT_BYTES ((2*A_PLANE + 2*BT_PLANE) * 4)   // 32256

template<int CIN, int COUT, bool PRE, bool POST>
__global__ void __launch_bounds__(256, 2) convT_mma_k(
    const float* __restrict__ in, const float* __restrict__ wh,
    const float* __restrict__ wl, const float* __restrict__ bias,
    float* __restrict__ out)
{
    extern __shared__ float smx[];
    float* sAh = smx;
    float* sAl = smx + A_PLANE;
    float* sBh = smx + 2 * A_PLANE;
    float* sBl = smx + 2 * A_PLANE + BT_PLANE;

    const int n    = blockIdx.z;
    const int oc0  = blockIdx.x * 64;
    const int cls  = blockIdx.y & 3;
    const int r0   = (blockIdx.y >> 2) * 4;   // oh' base (of 32)
    const int po   = cls >> 1;
    const int pw   = cls & 1;
    const int tid  = threadIdx.x;
    const int warp = tid >> 5;
    const int lane = tid & 31;
    const int wm   = warp >> 1;
    const int wn   = (warp & 1) * 32;
    const int gq   = lane >> 2;
    const int tg   = lane & 3;

    const float* inp = in + (size_t)n * CIN * 1024;

    float acc[2][4][4];
#pragma unroll
    for (int mt = 0; mt < 2; mt++)
#pragma unroll
        for (int nt = 0; nt < 4; nt++)
#pragma unroll
            for (int i = 0; i < 4; i++) acc[mt][nt][i] = 0.f;

    const int NCH = CIN / 8;
    for (int ch = 0; ch < NCH; ch++) {
        const int ci0 = ch * 8;

        for (int idx = tid; idx < A_PLANE; idx += 256) {
            int ci  = idx / 216;
            int rem = idx - ci * 216;
            int r   = rem / 36;
            int c   = rem - r * 36;
            int ih  = r0 - 1 + r;
            int iw  = c - 1;
            float v = 0.f;
            if (c < 34 && (unsigned)ih < 32u && (unsigned)iw < 32u)
                v = inp[(size_t)(ci0 + ci) * 1024 + ih * 32 + iw];
            if (PRE) v = fmaxf(v, 0.f);
            float hi = tf32_rna(v);
            sAh[idx] = hi;
            sAl[idx] = tf32_rna(v - hi);
        }

        for (int idx = tid; idx < 512; idx += 256) {
            int row = idx >> 4;
            int c4  = idx & 15;
            int tap = row >> 3;
            int ci  = row & 7;
            size_t g = (size_t)((cls * 4 + tap) * CIN + ci0 + ci) * COUT + oc0 + 4 * c4;
            int s = row * 72 + 4 * c4;
            *reinterpret_cast<float4*>(sBh + s) =
                *reinterpret_cast<const float4*>(wh + g);
            *reinterpret_cast<float4*>(sBl + s) =
                *reinterpret_cast<const float4*>(wl + g);
        }
        __syncthreads();

#pragma unroll
        for (int tap = 0; tap < 4; tap++) {
            const int khi = tap >> 1, kwi = tap & 1;
            const int rloc = wm + 1 + (po ? (1 - khi) : -khi);
            const int cloc = 1 + (pw ? (1 - kwi) : -kwi);
            unsigned bh[8], bl[8];
            const int bbase = (tap * 8 + tg) * 72 + wn + gq;
#pragma unroll
            for (int nt = 0; nt < 4; nt++) {
                bh[2*nt]   = __float_as_uint(sBh[bbase + 8 * nt]);
                bh[2*nt+1] = __float_as_uint(sBh[bbase + 288 + 8 * nt]);
                bl[2*nt]   = __float_as_uint(sBl[bbase + 8 * nt]);
                bl[2*nt+1] = __float_as_uint(sBl[bbase + 288 + 8 * nt]);
            }
#pragma unroll
            for (int mt = 0; mt < 2; mt++) {
                const int ab = tg * 216 + rloc * 36 + mt * 16 + gq + cloc;
                unsigned ah[4], al[4];
                ah[0] = __float_as_uint(sAh[ab]);
                ah[1] = __float_as_uint(sAh[ab + 8]);
                ah[2] = __float_as_uint(sAh[ab + 864]);
                ah[3] = __float_as_uint(sAh[ab + 872]);
                al[0] = __float_as_uint(sAl[ab]);
                al[1] = __float_as_uint(sAl[ab + 8]);
                al[2] = __float_as_uint(sAl[ab + 864]);
                al[3] = __float_as_uint(sAl[ab + 872]);
#pragma unroll
                for (int nt = 0; nt < 4; nt++) mma_tf32(acc[mt][nt], ah, bh + 2*nt);
#pragma unroll
                for (int nt = 0; nt < 4; nt++) mma_tf32(acc[mt][nt], ah, bl + 2*nt);
#pragma unroll
                for (int nt = 0; nt < 4; nt++) mma_tf32(acc[mt][nt], al, bh + 2*nt);
            }
        }
        __syncthreads();
    }

    const int gr = 2 * (r0 + wm) + po;          // output row (of 64)
#pragma unroll
    for (int mt = 0; mt < 2; mt++) {
        const int cb = mt * 16 + gq;
#pragma unroll
        for (int nt = 0; nt < 4; nt++) {
            const int ocb = oc0 + wn + nt * 8 + 2 * tg;
            float bv0 = bias[ocb];
            float bv1 = bias[ocb + 1];
            float d0 = acc[mt][nt][0] + bv0;
            float d1 = acc[mt][nt][1] + bv1;
            float d2 = acc[mt][nt][2] + bv0;
            float d3 = acc[mt][nt][3] + bv1;
            if (POST) {
                d0 = fmaxf(d0, 0.f); d1 = fmaxf(d1, 0.f);
                d2 = fmaxf(d2, 0.f); d3 = fmaxf(d3, 0.f);
            }
            float* o0 = out + ((size_t)(n * COUT + ocb)) * 4096 + gr * 64;
            float* o1 = o0 + 4096;
            o0[2 * cb + pw]      = d0;
            o1[2 * cb + pw]      = d1;
            o0[2 * cb + 16 + pw] = d2;
            o1[2 * cb + 16 + pw] = d3;
        }
    }
}

// ---------------------------------------------------------------------------
// 4x4 stride-2 pad-1 conv, f32x2 packed (enc1 only, CIN=3).
// ---------------------------------------------------------------------------
template<int CIN, int COUT, int HIN, int HOUT, bool POST>
__global__ void __launch_bounds__(128, 3) conv4x4s2_k(
    const float* __restrict__ in, const float* __restrict__ w,
    const float* __restrict__ bias, float* __restrict__ out)
{
    extern __shared__ char dsm[];
    ull*   s_w2  = (ull*)dsm;
    float* s_in0 = (float*)(dsm + (size_t)CIN * 4 * 16 * 8);
    float* s_in1 = s_in0 + 66 * 66;

    const int n   = blockIdx.z;
    const int oc0 = blockIdx.x * 4;
    const int TB  = HOUT / 32;
    const int r0  = (blockIdx.y / TB) * 32;
    const int c0  = (blockIdx.y % TB) * 32;
    const int tid = threadIdx.x;
    const int loh0 = (tid >> 3) * 2;
    const int low0 = (tid & 7) * 4;

    for (int i = tid; i < 4 * CIN * 16; i += 128) {
        int oc = i / (CIN * 16);
        int r  = i - oc * (CIN * 16);
        int ci = r / 16, kk = r - ci * 16;
        float v = w[(size_t)(oc0 + oc) * CIN * 16 + r];
        s_w2[(ci * 4 + oc) * 16 + kk] = pk2(v, v);
    }

    const int ihb = 2 * r0 - 1, iwb = 2 * c0 - 1;
    const float* inp = in + (size_t)n * CIN * HIN * HIN;

    for (int idx = tid; idx < 66 * 66; idx += 128) {
        int r = idx / 66, c = idx - r * 66;
        int ih = ihb + r, iw = iwb + c;
        float v = 0.f;
        if ((unsigned)ih < (unsigned)HIN && (unsigned)iw < (unsigned)HIN)
            v = inp[(size_t)ih * HIN + iw];
        s_in0[idx] = v;
    }
    __syncthreads();

    ull acc[4][4];
#pragma unroll
    for (int a = 0; a < 4; a++)
#pragma unroll
        for (int q = 0; q < 4; q++) acc[a][q] = 0ULL;

    for (int ci = 0; ci < CIN; ci++) {
        const float* cur = (ci & 1) ? s_in1 : s_in0;
        if (ci + 1 < CIN) {
            float* nb = ((ci + 1) & 1) ? s_in1 : s_in0;
            const float* inn = inp + (size_t)(ci + 1) * HIN * HIN;
            for (int idx = tid; idx < 66 * 66; idx += 128) {
                int r = idx / 66, c = idx - r * 66;
                int ih = ihb + r, iw = iwb + c;
                float v = 0.f;
                if ((unsigned)ih < (unsigned)HIN && (unsigned)iw < (unsigned)HIN)
                    v = inn[(size_t)ih * HIN + iw];
                nb[idx] = v;
            }
        }

        const int rowA0 = 2 * loh0;
        const int base  = 2 * low0;
        const ull* wci  = s_w2 + ci * 64;
#pragma unroll
        for (int kh = 0; kh < 4; kh++) {
            const float* pa = cur + (rowA0 + kh) * 66 + base;
            const float* pb = pa + 132;
            ull P[10];
#pragma unroll
            for (int c = 0; c < 10; c++) P[c] = pk2(pa[c], pb[c]);
#pragma unroll
            for (int oc = 0; oc < 4; oc++)
#pragma unroll
                for (int kw = 0; kw < 4; kw++) {
                    ull w2 = wci[oc * 16 + kh * 4 + kw];
#pragma unroll
                    for (int pw = 0; pw < 4; pw++)
                        fma2(acc[oc][pw], P[2 * pw + kw], w2);
                }
        }
        __syncthreads();
    }

#pragma unroll
    for (int oc = 0; oc < 4; oc++) {
        float bv = bias[oc0 + oc];
        float* obase = out + ((size_t)(n * COUT + oc0 + oc)) * HOUT * HOUT +
                       (size_t)(r0 + loh0) * HOUT + (c0 + low0);
#pragma unroll
        for (int pw = 0; pw < 4; pw++) {
            float2 v = unpk(acc[oc][pw]);
            v.x += bv; v.y += bv;
            if (POST) { v.x = fmaxf(v.x, 0.f); v.y = fmaxf(v.y, 0.f); }
            obase[pw]        = v.x;
            obase[HOUT + pw] = v.y;
        }
    }
}

// ---------------------------------------------------------------------------
// ConvTranspose2d k=4 s=2 p=1, f32x2 packed (tc2 only).
// ---------------------------------------------------------------------------
template<int CIN, int COUT, int OCB, int HIN, int HOUT, bool PRE, bool POST>
__global__ void __launch_bounds__(128, 4) convT4x4s2_k(
    const float* __restrict__ in, const float* __restrict__ w,
    const float* __restrict__ bias, float* __restrict__ out)
{
    const int n   = blockIdx.z;
    const int oc0 = blockIdx.x * OCB;
    const int TB  = HOUT / 32;
    const int r0  = (blockIdx.y / TB) * 32;
    const int c0  = (blockIdx.y % TB) * 32;
    const int tid = threadIdx.x;
    const int loh0 = (tid >> 3) * 2;
    const int low0 = (tid & 7) * 4;

    __shared__ float s_in[2][18 * 18];
    __shared__ ull   s_w2[CIN * OCB * 8];

    for (int i = tid; i < CIN * OCB * 8; i += 128) {
        int per = OCB * 8;
        int ci = i / per;
        int r  = i - ci * per;
        int oc = r >> 3;
        int t  = r & 7;
        int kw = t >> 1, p = t & 1;
        const float* wb = w + ((size_t)ci * COUT + oc0 + oc) * 16;
        s_w2[i] = pk2(wb[(p * 2 + 1) * 4 + kw], wb[(p * 2) * 4 + kw]);
    }

    const int ihb = (r0 - 2) / 2;
    const int iwb = (c0 - 2) / 2;
    const float* inp = in + (size_t)n * CIN * HIN * HIN;

    int goff[3];
#pragma unroll
    for (int s = 0; s < 3; s++) {
        int idx = tid + s * 128;
        int r = idx / 18, c = idx - r * 18;
        int ih = ihb + r, iw = iwb + c;
        goff[s] = ((unsigned)ih < (unsigned)HIN && (unsigned)iw < (unsigned)HIN)
                      ? ih * HIN + iw : -1;
    }

    {
        float* b0 = s_in[0];
#pragma unroll
        for (int s = 0; s < 2; s++) {
            float v = (goff[s] >= 0) ? inp[goff[s]] : 0.f;
            if (PRE) v = fmaxf(v, 0.f);
            b0[tid + s * 128] = v;
        }
        if (tid < 68) {
            float v = (goff[2] >= 0) ? inp[goff[2]] : 0.f;
            if (PRE) v = fmaxf(v, 0.f);
            b0[tid + 256] = v;
        }
    }
    __syncthreads();

    ull acc[OCB][4];
#pragma unroll
    for (int a = 0; a < OCB; a++)
#pragma unroll
        for (int q = 0; q < 4; q++) acc[a][q] = 0ULL;

    const int rb = loh0 >> 1;
    const int cb = low0 >> 1;

    for (int ci = 0; ci < CIN; ci++) {
        const float* cur = s_in[ci & 1];
        if (ci + 1 < CIN) {
            const float* inn = inp + (size_t)(ci + 1) * HIN * HIN;
            float* nb = s_in[(ci + 1) & 1];
#pragma unroll
            for (int s = 0; s < 2; s++) {
                float v = (goff[s] >= 0) ? inn[goff[s]] : 0.f;
                if (PRE) v = fmaxf(v, 0.f);
                nb[tid + s * 128] = v;
            }
            if (tid < 68) {
                float v = (goff[2] >= 0) ? inn[goff[2]] : 0.f;
                if (PRE) v = fmaxf(v, 0.f);
                nb[tid + 256] = v;
            }
        }

        ull A[4], B[4];
#pragma unroll
        for (int c = 0; c < 4; c++) {
            float x0 = cur[rb * 18 + cb + c];
            float x1 = cur[(rb + 1) * 18 + cb + c];
            float x2 = cur[(rb + 2) * 18 + cb + c];
            A[c] = pk2(x1, x2);
            B[c] = pk2(x0, x1);
        }

        const ull* wci = s_w2 + ci * OCB * 8;
#pragma unroll
        for (int oc = 0; oc < OCB; oc++) {
            const ull* wp = wci + oc * 8;
#pragma unroll
            for (int pw = 0; pw < 4; pw++) {
                const int kwh = (pw & 1) ? 0 : 1;
                const int rh  = (pw >> 1) + 1 + (pw & 1);
                fma2(acc[oc][pw], A[rh],     wp[kwh * 2 + 0]);
                fma2(acc[oc][pw], B[rh],     wp[kwh * 2 + 1]);
                fma2(acc[oc][pw], A[rh - 1], wp[(kwh + 2) * 2 + 0]);
                fma2(acc[oc][pw], B[rh - 1], wp[(kwh + 2) * 2 + 1]);
            }
        }
        __syncthreads();
    }

#pragma unroll
    for (int oc = 0; oc < OCB; oc++) {
        float bv = bias[oc0 + oc];
        float* obase = out + ((size_t)(n * COUT + oc0 + oc)) * HOUT * HOUT +
                       (size_t)(r0 + loh0) * HOUT + (c0 + low0);
#pragma unroll
        for (int pw = 0; pw < 4; pw++) {
            float2 v = unpk(acc[oc][pw]);
            v.x += bv; v.y += bv;
            if (POST) { v.x = fmaxf(v.x, 0.f); v.y = fmaxf(v.y, 0.f); }
            obase[pw]        = v.x;
            obase[HOUT + pw] = v.y;
        }
    }
}

// ---------------------------------------------------------------------------
// 1x1 conv on 32x32 images.
// ---------------------------------------------------------------------------
template<int CIN, int COUT, bool PRE, bool BIAS, bool ADDRES>
__global__ void __launch_bounds__(256) conv1x1_k(
    const float* __restrict__ in, const float* __restrict__ w,
    const float* __restrict__ bias, float* __restrict__ out)
{
    const int n   = blockIdx.y;
    const int oc0 = blockIdx.x * 4;
    const int tid = threadIdx.x;
    const int hw0 = tid * 4;

    __shared__ float s_w[4 * CIN];
    for (int i = tid; i < 4 * CIN; i += 256)
        s_w[i] = w[(oc0 + i / CIN) * CIN + (i % CIN)];
    __syncthreads();

    float acc[4][4];
#pragma unroll
    for (int a = 0; a < 4; a++)
#pragma unroll
        for (int q = 0; q < 4; q++) acc[a][q] = 0.f;

    const float* inp = in + (size_t)n * CIN * 1024 + hw0;
    for (int ci = 0; ci < CIN; ci++) {
        float4 v = *reinterpret_cast<const float4*>(inp + (size_t)ci * 1024);
        if (PRE) {
            v.x = fmaxf(v.x, 0.f); v.y = fmaxf(v.y, 0.f);
            v.z = fmaxf(v.z, 0.f); v.w = fmaxf(v.w, 0.f);
        }
#pragma unroll
        for (int oc = 0; oc < 4; oc++) {
            float wv = s_w[oc * CIN + ci];
            acc[oc][0] = fmaf(v.x, wv, acc[oc][0]);
            acc[oc][1] = fmaf(v.y, wv, acc[oc][1]);
            acc[oc][2] = fmaf(v.z, wv, acc[oc][2]);
            acc[oc][3] = fmaf(v.w, wv, acc[oc][3]);
        }
    }

#pragma unroll
    for (int oc = 0; oc < 4; oc++) {
        float bv = BIAS ? bias[oc0 + oc] : 0.f;
        float* op = out + ((size_t)(n * COUT + oc0 + oc)) * 1024 + hw0;
        float4 o;
        o.x = acc[oc][0] + bv; o.y = acc[oc][1] + bv;
        o.z = acc[oc][2] + bv; o.w = acc[oc][3] + bv;
        if (ADDRES) {
            float4 r = *reinterpret_cast<const float4*>(op);
            o.x += r.x; o.y += r.y; o.z += r.z; o.w += r.w;
        }
        *reinterpret_cast<float4*>(op) = o;
    }
}

// ---------------------------------------------------------------------------
// Vector quantizer.
// ---------------------------------------------------------------------------
#define VQ_SMEM ((32768 + 512 + 512 + 256) * 4)

__global__ void __launch_bounds__(256) vq_k(
    const float* __restrict__ ze, const float* __restrict__ E,
    float* __restrict__ zq, int* __restrict__ hist, float* __restrict__ mse)
{
    extern __shared__ float sm[];
    float* sE   = sm;
    float* sEsq = sm + 32768;
    int*   sHist= (int*)(sm + 33280);
    float* sRed = sm + 33792;

    const int tid = threadIdx.x;
    for (int i = tid; i < VQ_K * VQ_D; i += 256) sE[i] = E[i];
    for (int i = tid; i < VQ_K; i += 256) sHist[i] = 0;
    __syncthreads();
    for (int i = tid; i < VQ_K; i += 256) {
        const float* e = &sE[i * VQ_D];
        float s = 0.f;
#pragma unroll 16
        for (int d = 0; d < VQ_D; d++) s = fmaf(e[d], e[d], s);
        sEsq[i] = s;
    }
    __syncthreads();

    const int p  = blockIdx.x * 256 + tid;
    const int n  = p >> 10;
    const int hw = p & 1023;
    const float* zp = ze + (size_t)n * VQ_D * 1024 + hw;

    float f[VQ_D];
#pragma unroll
    for (int d = 0; d < VQ_D; d++) f[d] = zp[(size_t)d * 1024];

    float best = 3.4e38f;
    int   bi   = 0;
    for (int k = 0; k < VQ_K; k++) {
        const float4* e4 = reinterpret_cast<const float4*>(&sE[k * VQ_D]);
        float s0 = 0.f, s1 = 0.f, s2 = 0.f, s3 = 0.f;
#pragma unroll
        for (int d = 0; d < VQ_D / 4; d++) {
            float4 e = e4[d];
            s0 = fmaf(e.x, f[4 * d + 0], s0);
            s1 = fmaf(e.y, f[4 * d + 1], s1);
            s2 = fmaf(e.z, f[4 * d + 2], s2);
            s3 = fmaf(e.w, f[4 * d + 3], s3);
        }
        float score = sEsq[k] - 2.f * ((s0 + s1) + (s2 + s3));
        if (score < best) { best = score; bi = k; }
    }

    const float* eb = &sE[bi * VQ_D];
    float* zqp = zq + (size_t)n * VQ_D * 1024 + hw;
    float md = 0.f;
#pragma unroll
    for (int d = 0; d < VQ_D; d++) {
        float ev = eb[d];
        float dd = f[d] - ev;
        md = fmaf(dd, dd, md);
        zqp[(size_t)d * 1024] = ev;
    }

    atomicAdd(&sHist[bi], 1);
    sRed[tid] = md;
    __syncthreads();
    for (int s = 128; s > 0; s >>= 1) {
        if (tid < s) sRed[tid] += sRed[tid + s];
        __syncthreads();
    }
    if (tid == 0) atomicAdd(mse, sRed[0]);
    for (int i = tid; i < VQ_K; i += 256) {
        int c = sHist[i];
        if (c) atomicAdd(&hist[i], c);
    }
}

__global__ void finalize_k(const int* __restrict__ hist,
                           const float* __restrict__ mse,
                           float* __restrict__ out)
{
    __shared__ float red[VQ_K];
    const int k = threadIdx.x;
    float pb = (float)hist[k] * (1.f / 65536.f);
    red[k] = pb * log2f(pb + 1e-10f);
    __syncthreads();
    for (int s = 256; s > 0; s >>= 1) {
        if (k < s) red[k] += red[k + s];
        __syncthreads();
    }
    if (k == 0) {
        float H = -red[0];
        float m = mse[0] * (1.f / (65536.f * 64.f));
        out[0]       = 1.25f * m;
        out[OUT_ELQ] = m;
        out[OUT_QLQ] = m;
        out[OUT_EW]  = exp2f(H);
    }
}

// ---------------------------------------------------------------------------
// Launch
// ---------------------------------------------------------------------------
extern "C" void kernel_launch(void* const* d_in, const int* in_sizes, int n_in,
                              void* d_out, int out_size)
{
    (void)in_sizes; (void)n_in; (void)out_size;
    const float* x          = (const float*)d_in[0];
    const float* enc_w1     = (const float*)d_in[1];
    const float* enc_b1     = (const float*)d_in[2];
    const float* enc_w2     = (const float*)d_in[3];
    const float* enc_b2     = (const float*)d_in[4];
    const float* enc_w3     = (const float*)d_in[5];
    const float* enc_b3     = (const float*)d_in[6];
    const float* enc_w4     = (const float*)d_in[7];
    const float* enc_b4     = (const float*)d_in[8];
    const float* enc_res_w1 = (const float*)d_in[9];
    const float* enc_res_w2 = (const float*)d_in[10];
    const float* enc_adj_w  = (const float*)d_in[11];
    const float* enc_adj_b  = (const float*)d_in[12];
    const float* E          = (const float*)d_in[13];
    const float* dec_adj_w  = (const float*)d_in[14];
    const float* dec_adj_b  = (const float*)d_in[15];
    const float* dec_res_w1 = (const float*)d_in[16];
    const float* dec_res_w2 = (const float*)d_in[17];
    const float* tc1_w      = (const float*)d_in[18];
    const float* tc1_b      = (const float*)d_in[19];
    const float* tc2_w      = (const float*)d_in[20];
    const float* tc2_b      = (const float*)d_in[21];
    float* out = (float*)d_out;

    float *h1, *a, *b, *mid, *ze, *zq, *mse, *wh, *wl; int* hist;
    cudaGetSymbolAddress((void**)&h1,  g_h1);
    cudaGetSymbolAddress((void**)&a,   g_a);
    cudaGetSymbolAddress((void**)&b,   g_b);
    cudaGetSymbolAddress((void**)&mid, g_mid);
    cudaGetSymbolAddress((void**)&ze,  g_ze);
    cudaGetSymbolAddress((void**)&zq,  g_zq);
    cudaGetSymbolAddress((void**)&wh,  g_wh);
    cudaGetSymbolAddress((void**)&wl,  g_wl);
    cudaGetSymbolAddress((void**)&mse, g_mse);
    cudaGetSymbolAddress((void**)&hist, g_hist);

    cudaFuncSetAttribute(vq_k, cudaFuncAttributeMaxDynamicSharedMemorySize, VQ_SMEM);

    const int SMEM_C1 = 3 * 4 * 16 * 8 + 2 * 66 * 66 * 4;   // 36384
    cudaFuncSetAttribute(conv4x4s2_k<3, 64, 128, 64, true>,
                         cudaFuncAttributeMaxDynamicSharedMemorySize, SMEM_C1);

    cudaFuncSetAttribute(conv3x3_mma_k<128, 128, false, true,  true>,
                         cudaFuncAttributeMaxDynamicSharedMemorySize, SM3_BYTES);
    cudaFuncSetAttribute(conv3x3_mma_k<128, 128, false, false, true>,
                         cudaFuncAttributeMaxDynamicSharedMemorySize, SM3_BYTES);
    cudaFuncSetAttribute(conv3x3_mma_k<128, 64, true, true, false>,
                         cudaFuncAttributeMaxDynamicSharedMemorySize, SM3_BYTES);
    cudaFuncSetAttribute(conv3x3_mma_k<64, 128, false, false, true>,
                         cudaFuncAttributeMaxDynamicSharedMemorySize, SM3_BYTES);
    cudaFuncSetAttribute(conv4x4s2_mma_k<64, 128, true>,
                         cudaFuncAttributeMaxDynamicSharedMemorySize, SM4_BYTES);
    cudaFuncSetAttribute(convT_mma_k<128, 64, true, true>,
                         cudaFuncAttributeMaxDynamicSharedMemorySize, SMT_BYTES);

    reset_k<<<1, 512>>>(hist, mse);

    // ---- Encoder ----
    conv4x4s2_k<3, 64, 128, 64, true><<<dim3(16, 4, BATCH), 128, SMEM_C1>>>(x, enc_w1, enc_b1, h1);

    wsplit4_k<<<288, 256>>>(enc_w2, 64, 128, wh, wl);
    conv4x4s2_mma_k<64, 128, true><<<dim3(2, 8, BATCH), 256, SM4_BYTES>>>(h1, wh, wl, enc_b2, a);

    wsplit_k<<<288, 256>>>(enc_w3, 128, 128, wh, wl);
    conv3x3_mma_k<128, 128, false, true,  true><<<dim3(2, 8, BATCH), 256, SM3_BYTES>>>(a, wh, wl, enc_b3, b);
    wsplit_k<<<288, 256>>>(enc_w4, 128, 128, wh, wl);
    conv3x3_mma_k<128, 128, false, false, true><<<dim3(2, 8, BATCH), 256, SM3_BYTES>>>(b, wh, wl, enc_b4, a);
    wsplit_k<<<288, 256>>>(enc_res_w1, 128, 64, wh, wl);
    conv3x3_mma_k<128, 64, true, true, false><<<dim3(1, 8, BATCH), 256, SM3_BYTES>>>(a, wh, wl, nullptr, mid);
    conv1x1_k<64, 128, false, false, true><<<dim3(32, BATCH), 256>>>(mid, enc_res_w2, nullptr, a);
    wsplit_k<<<288, 256>>>(enc_res_w1 + 64 * 128 * 9, 128, 64, wh, wl);
    conv3x3_mma_k<128, 64, true, true, false><<<dim3(1, 8, BATCH), 256, SM3_BYTES>>>(a, wh, wl, nullptr, mid);
    conv1x1_k<64, 128, false, false, true><<<dim3(32, BATCH), 256>>>(mid, enc_res_w2 + 128 * 64, nullptr, a);
    conv1x1_k<128, 64, true, true, false><<<dim3(16, BATCH), 256>>>(a, enc_adj_w, enc_adj_b, ze);

    // ---- Vector quantizer ----
    vq_k<<<256, 256, VQ_SMEM>>>(ze, E, zq, hist, mse);
    finalize_k<<<1, 512>>>(hist, mse, out);

    // ---- Decoder ----
    wsplit_k<<<288, 256>>>(dec_adj_w, 64, 128, wh, wl);
    conv3x3_mma_k<64, 128, false, false, true><<<dim3(2, 8, BATCH), 256, SM3_BYTES>>>(zq, wh, wl, dec_adj_b, a);
    wsplit_k<<<288, 256>>>(dec_res_w1, 128, 64, wh, wl);
    conv3x3_mma_k<128, 64, true, true, false><<<dim3(1, 8, BATCH), 256, SM3_BYTES>>>(a, wh, wl, nullptr, mid);
    conv1x1_k<64, 128, false, false, true><<<dim3(32, BATCH), 256>>>(mid, dec_res_w2, nullptr, a);
    wsplit_k<<<288, 256>>>(dec_res_w1 + 64 * 128 * 9, 128, 64, wh, wl);
    conv3x3_mma_k<128, 64, true, true, false><<<dim3(1, 8, BATCH), 256, SM3_BYTES>>>(a, wh, wl, nullptr, mid);
    conv1x1_k<64, 128, false, false, true><<<dim3(32, BATCH), 256>>>(mid, dec_res_w2 + 128 * 64, nullptr, a);

    wsplitT_k<<<288, 256>>>(tc1_w, 128, 64, wh, wl);
    convT_mma_k<128, 64, true, true><<<dim3(1, 32, BATCH), 256, SMT_BYTES>>>(a, wh, wl, tc1_b, h1);

    convT4x4s2_k<64, 3, 3, 64, 128, false, false><<<dim3(1, 16, BATCH), 128>>>(h1, tc2_w, tc2_b, out + OUT_RECON_OFF);
}

// round 13
// speedup vs baseline: 1.0011x; 1.0010x over previous
#include <cuda_runtime.h>
#include <math.h>
#include <stdint.h>

// ---------------------------------------------------------------------------
// VQ-VAE forward. 3x3 convs, enc2 (4x4 s2), tc1 (convT 4x4 s2) via
// split-precision TF32 mma.sync implicit GEMM; rest fp32 FFMA2.
// Output layout (float32, 3145732 elems):
//   [0] e_and_q  [1..3145728] x_recon  [3145729] e_latent  [3145730] q_latent
//   [3145731] est_words
// ---------------------------------------------------------------------------

#define BATCH 64
#define VQ_K 512
#define VQ_D 64
#define OUT_RECON_OFF 1
#define OUT_RECON_N   (64*3*128*128)
#define OUT_ELQ  (OUT_RECON_OFF + OUT_RECON_N)
#define OUT_QLQ  (OUT_ELQ + 1)
#define OUT_EW   (OUT_QLQ + 1)

typedef unsigned long long ull;

// ---- packed f32x2 helpers --------------------------------------------------
__device__ __forceinline__ ull pk2(float lo, float hi) {
    ull r; asm("mov.b64 %0, {%1, %2};" : "=l"(r) : "f"(lo), "f"(hi)); return r;
}
__device__ __forceinline__ float2 unpk(ull v) {
    float2 r; asm("mov.b64 {%0, %1}, %2;" : "=f"(r.x), "=f"(r.y) : "l"(v)); return r;
}
__device__ __forceinline__ void fma2(ull& d, ull a, ull b) {
    asm("fma.rn.f32x2 %0, %1, %2, %0;" : "+l"(d) : "l"(a), "l"(b));
}

// ---- tf32 helpers ----------------------------------------------------------
__device__ __forceinline__ float tf32_rna(float x) {
    unsigned u; asm("cvt.rna.tf32.f32 %0, %1;" : "=r"(u) : "f"(x));
    return __uint_as_float(u);
}
__device__ __forceinline__ void mma_tf32(float* d, const unsigned* a, const unsigned* b) {
    asm volatile(
        "mma.sync.aligned.m16n8k8.row.col.f32.tf32.tf32.f32 "
        "{%0,%1,%2,%3}, {%4,%5,%6,%7}, {%8,%9}, {%0,%1,%2,%3};\n"
        : "+f"(d[0]), "+f"(d[1]), "+f"(d[2]), "+f"(d[3])
        : "r"(a[0]), "r"(a[1]), "r"(a[2]), "r"(a[3]), "r"(b[0]), "r"(b[1]));
}

// ---------------- scratch buffers -------------------------------------------
__device__ float g_h1 [64*64*64*64];
__device__ float g_a  [64*128*32*32];
__device__ float g_b  [64*128*32*32];
__device__ float g_mid[64*64*32*32];
__device__ float g_ze [64*64*32*32];
__device__ float g_zq [64*64*32*32];
__device__ float g_wh [128*128*9];     // split weights (hi)
__device__ float g_wl [128*128*9];     // split weights (lo)
__device__ int   g_hist[VQ_K];
__device__ float g_mse[1];

__global__ void reset_k(int* hist, float* mse) {
    int t = threadIdx.x;
    if (t < VQ_K) hist[t] = 0;
    if (t == 0)   mse[0] = 0.f;
}

// ---------------------------------------------------------------------------
// Weight pre-splits.
// ---------------------------------------------------------------------------
// 3x3 conv, OIHW -> [tap*CIN+ci][oc]
__global__ void wsplit_k(const float* __restrict__ w, int CIN, int COUT,
                         float* __restrict__ wh, float* __restrict__ wl)
{
    int total = COUT * CIN * 9;
    for (int j = blockIdx.x * blockDim.x + threadIdx.x; j < total;
         j += gridDim.x * blockDim.x) {
        int row = j / COUT;
        int oc  = j - row * COUT;
        int tap = row / CIN;
        int ci  = row - tap * CIN;
        float v = w[((size_t)oc * CIN + ci) * 9 + tap];
        float hi = tf32_rna(v);
        wh[j] = hi;
        wl[j] = tf32_rna(v - hi);
    }
}

// 4x4 conv, OIHW -> [tap*CIN+ci][oc], tap = kh*4+kw
__global__ void wsplit4_k(const float* __restrict__ w, int CIN, int COUT,
                          float* __restrict__ wh, float* __restrict__ wl)
{
    int total = COUT * CIN * 16;
    for (int j = blockIdx.x * blockDim.x + threadIdx.x; j < total;
         j += gridDim.x * blockDim.x) {
        int row = j / COUT;
        int oc  = j - row * COUT;
        int tap = row / CIN;
        int ci  = row - tap * CIN;
        float v = w[((size_t)oc * CIN + ci) * 16 + tap];
        float hi = tf32_rna(v);
        wh[j] = hi;
        wl[j] = tf32_rna(v - hi);
    }
}

// convT 4x4, (CIN,COUT,kh,kw) -> [(class*4+tap)*CIN+ci][oc]
// class = po*2+pw (output parities), tap = khi*2+kwi,
// kh = ((po+1)&1)+2*khi, kw = ((pw+1)&1)+2*kwi
__global__ void wsplitT_k(const float* __restrict__ w, int CIN, int COUT,
                          float* __restrict__ wh, float* __restrict__ wl)
{
    int total = 16 * CIN * COUT;
    for (int j = blockIdx.x * blockDim.x + threadIdx.x; j < total;
         j += gridDim.x * blockDim.x) {
        int row = j / COUT;
        int oc  = j - row * COUT;
        int ct  = row / CIN;
        int ci  = row - ct * CIN;
        int cls = ct >> 2, tap = ct & 3;
        int po = cls >> 1, pw = cls & 1;
        int kh = ((po + 1) & 1) + 2 * (tap >> 1);
        int kw = ((pw + 1) & 1) + 2 * (tap & 1);
        float v = w[((size_t)ci * COUT + oc) * 16 + kh * 4 + kw];
        float hi = tf32_rna(v);
        wh[j] = hi;
        wl[j] = tf32_rna(v - hi);
    }
}

// ---------------------------------------------------------------------------
// 3x3 stride-1 pad-1 conv on 32x32 via split-TF32 mma (3xTF32).
// grid(COUT/64, 8, B), block 256. CTA tile M=128 (4 rows x 32), N=64.
// smem: A hi/lo [8ci][6r][36c]; B hi/lo [72][72].
// ---------------------------------------------------------------------------
#define A_PLANE 1728
#define B_PLANE 5184
#define SM3_BYTES ((2*A_PLANE + 2*B_PLANE) * 4)    // 55296

template<int CIN, int COUT, bool PRE, bool POST, bool BIAS>
__global__ void __launch_bounds__(256, 2) conv3x3_mma_k(
    const float* __restrict__ in, const float* __restrict__ wh,
    const float* __restrict__ wl, const float* __restrict__ bias,
    float* __restrict__ out)
{
    extern __shared__ float smx[];
    float* sAh = smx;
    float* sAl = smx + A_PLANE;
    float* sBh = smx + 2 * A_PLANE;
    float* sBl = smx + 2 * A_PLANE + B_PLANE;

    const int n    = blockIdx.z;
    const int oc0  = blockIdx.x * 64;
    const int r0g  = blockIdx.y * 4;
    const int tid  = threadIdx.x;
    const int warp = tid >> 5;
    const int lane = tid & 31;
    const int wm   = warp >> 1;
    const int wn   = (warp & 1) * 32;
    const int gq   = lane >> 2;
    const int tg   = lane & 3;

    const float* inp = in + (size_t)n * CIN * 1024;

    float acc[2][4][4];
#pragma unroll
    for (int mt = 0; mt < 2; mt++)
#pragma unroll
        for (int nt = 0; nt < 4; nt++)
#pragma unroll
            for (int i = 0; i < 4; i++) acc[mt][nt][i] = 0.f;

    const int NCH = CIN / 8;
    for (int ch = 0; ch < NCH; ch++) {
        const int ci0 = ch * 8;

        for (int idx = tid; idx < A_PLANE; idx += 256) {
            int ci  = idx / 216;
            int rem = idx - ci * 216;
            int r   = rem / 36;
            int c   = rem - r * 36;
            int ih  = r0g - 1 + r;
            int iw  = c - 1;
            float v = 0.f;
            if (c < 34 && (unsigned)ih < 32u && (unsigned)iw < 32u)
                v = inp[(size_t)(ci0 + ci) * 1024 + ih * 32 + iw];
            if (PRE) v = fmaxf(v, 0.f);
            float hi = tf32_rna(v);
            sAh[idx] = hi;
            sAl[idx] = tf32_rna(v - hi);
        }

        for (int idx = tid; idx < 1152; idx += 256) {
            int row = idx >> 4;
            int c4  = idx & 15;
            int tap = row >> 3;
            int ci  = row & 7;
            size_t g = (size_t)(tap * CIN + ci0 + ci) * COUT + oc0 + 4 * c4;
            int s = row * 72 + 4 * c4;
            *reinterpret_cast<float4*>(sBh + s) =
                *reinterpret_cast<const float4*>(wh + g);
            *reinterpret_cast<float4*>(sBl + s) =
                *reinterpret_cast<const float4*>(wl + g);
        }
        __syncthreads();

#pragma unroll
        for (int kh = 0; kh < 3; kh++)
#pragma unroll
            for (int kw = 0; kw < 3; kw++) {
                const int tap = kh * 3 + kw;
                unsigned bh[8], bl[8];
                const int bbase = (tap * 8 + tg) * 72 + wn + gq;
#pragma unroll
                for (int nt = 0; nt < 4; nt++) {
                    bh[2*nt]   = __float_as_uint(sBh[bbase + 8 * nt]);
                    bh[2*nt+1] = __float_as_uint(sBh[bbase + 288 + 8 * nt]);
                    bl[2*nt]   = __float_as_uint(sBl[bbase + 8 * nt]);
                    bl[2*nt+1] = __float_as_uint(sBl[bbase + 288 + 8 * nt]);
                }
#pragma unroll
                for (int mt = 0; mt < 2; mt++) {
                    const int ab = tg * 216 + (wm + kh) * 36 + mt * 16 + gq + kw;
                    unsigned ah[4], al[4];
                    ah[0] = __float_as_uint(sAh[ab]);
                    ah[1] = __float_as_uint(sAh[ab + 8]);
                    ah[2] = __float_as_uint(sAh[ab + 864]);
                    ah[3] = __float_as_uint(sAh[ab + 872]);
                    al[0] = __float_as_uint(sAl[ab]);
                    al[1] = __float_as_uint(sAl[ab + 8]);
                    al[2] = __float_as_uint(sAl[ab + 864]);
                    al[3] = __float_as_uint(sAl[ab + 872]);
#pragma unroll
                    for (int nt = 0; nt < 4; nt++) mma_tf32(acc[mt][nt], ah, bh + 2*nt);
#pragma unroll
                    for (int nt = 0; nt < 4; nt++) mma_tf32(acc[mt][nt], ah, bl + 2*nt);
#pragma unroll
                    for (int nt = 0; nt < 4; nt++) mma_tf32(acc[mt][nt], al, bh + 2*nt);
                }
            }
        __syncthreads();
    }

    const int gr = r0g + wm;
#pragma unroll
    for (int mt = 0; mt < 2; mt++) {
        const int cb = mt * 16 + gq;
#pragma unroll
        for (int nt = 0; nt < 4; nt++) {
            const int ocb = oc0 + wn + nt * 8 + 2 * tg;
            float bv0 = BIAS ? bias[ocb]     : 0.f;
            float bv1 = BIAS ? bias[ocb + 1] : 0.f;
            float d0 = acc[mt][nt][0] + bv0;
            float d1 = acc[mt][nt][1] + bv1;
            float d2 = acc[mt][nt][2] + bv0;
            float d3 = acc[mt][nt][3] + bv1;
            if (POST) {
                d0 = fmaxf(d0, 0.f); d1 = fmaxf(d1, 0.f);
                d2 = fmaxf(d2, 0.f); d3 = fmaxf(d3, 0.f);
            }
            float* o0 = out + ((size_t)(n * COUT + ocb)) * 1024 + gr * 32;
            float* o1 = o0 + 1024;
            o0[cb]     = d0;
            o1[cb]     = d1;
            o0[cb + 8] = d2;
            o1[cb + 8] = d3;
        }
    }
}

// ---------------------------------------------------------------------------
// 4x4 stride-2 pad-1 conv (HIN=64 -> HOUT=32) via split-TF32 mma.
// grid(COUT/64, 8, B), block 256. A tile split by input-col parity:
// half h: iw = 2j-1+h. Layout [h][8ci][10r][36c] (plane 360 -> conflict-free).
// Taps staged in 2 groups of 8 (B group = 64 rows x 72).
// ---------------------------------------------------------------------------
#define A4_HALF  2880
#define A4_PLANE (2*A4_HALF)           // 5760
#define B4_PLANE (64*72)               // 4608
#define SM4_BYTES ((2*A4_PLANE + 2*B4_PLANE) * 4)   // 82944

template<int CIN, int COUT, bool POST>
__global__ void __launch_bounds__(256, 2) conv4x4s2_mma_k(
    const float* __restrict__ in, const float* __restrict__ wh,
    const float* __restrict__ wl, const float* __restrict__ bias,
    float* __restrict__ out)
{
    extern __shared__ float smx[];
    float* sAh = smx;
    float* sAl = smx + A4_PLANE;
    float* sBh = smx + 2 * A4_PLANE;
    float* sBl = smx + 2 * A4_PLANE + B4_PLANE;

    const int n    = blockIdx.z;
    const int oc0  = blockIdx.x * 64;
    const int r0   = blockIdx.y * 4;     // output rows (of 32)
    const int tid  = threadIdx.x;
    const int warp = tid >> 5;
    const int lane = tid & 31;
    const int wm   = warp >> 1;
    const int wn   = (warp & 1) * 32;
    const int gq   = lane >> 2;
    const int tg   = lane & 3;

    const float* inp = in + (size_t)n * CIN * 4096;

    float acc[2][4][4];
#pragma unroll
    for (int mt = 0; mt < 2; mt++)
#pragma unroll
        for (int nt = 0; nt < 4; nt++)
#pragma unroll
            for (int i = 0; i < 4; i++) acc[mt][nt][i] = 0.f;

    const int NCH = CIN / 8;
    for (int ch = 0; ch < NCH; ch++) {
        const int ci0 = ch * 8;

        // stage A (both parity halves)
        for (int idx = tid; idx < A4_PLANE; idx += 256) {
            int h   = idx / A4_HALF;
            int rem = idx - h * A4_HALF;
            int ci  = rem / 360;
            int r2  = rem - ci * 360;
            int r   = r2 / 36;
            int j   = r2 - r * 36;
            int ih  = 2 * r0 - 1 + r;
            int iw  = 2 * j - 1 + h;
            float v = 0.f;
            if ((unsigned)ih < 64u && (unsigned)iw < 64u)
                v = inp[(size_t)(ci0 + ci) * 4096 + ih * 64 + iw];
            float hi = tf32_rna(v);
            sAh[idx] = hi;
            sAl[idx] = tf32_rna(v - hi);
        }

#pragma unroll
        for (int ggrp = 0; ggrp < 2; ggrp++) {
            // stage B group (taps ggrp*8 .. ggrp*8+7)
            for (int idx = tid; idx < 1024; idx += 256) {
                int row = idx >> 4;
                int c4  = idx & 15;
                int tap = ggrp * 8 + (row >> 3);
                int ci  = row & 7;
                size_t g = (size_t)(tap * CIN + ci0 + ci) * COUT + oc0 + 4 * c4;
                int s = row * 72 + 4 * c4;
                *reinterpret_cast<float4*>(sBh + s) =
                    *reinterpret_cast<const float4*>(wh + g);
                *reinterpret_cast<float4*>(sBl + s) =
                    *reinterpret_cast<const float4*>(wl + g);
            }
            __syncthreads();

#pragma unroll
            for (int tl = 0; tl < 8; tl++) {
                const int t  = ggrp * 8 + tl;
                const int kh = t >> 2;
                const int kw = t & 3;
                const int h  = kw & 1;          // kw odd -> even iw half
                const int joff = kw >> 1;
                unsigned bh[8], bl[8];
                const int bbase = (tl * 8 + tg) * 72 + wn + gq;
#pragma unroll
                for (int nt = 0; nt < 4; nt++) {
                    bh[2*nt]   = __float_as_uint(sBh[bbase + 8 * nt]);
                    bh[2*nt+1] = __float_as_uint(sBh[bbase + 288 + 8 * nt]);
                    bl[2*nt]   = __float_as_uint(sBl[bbase + 8 * nt]);
                    bl[2*nt+1] = __float_as_uint(sBl[bbase + 288 + 8 * nt]);
                }
#pragma unroll
                for (int mt = 0; mt < 2; mt++) {
                    const int ab = h * A4_HALF + tg * 360 + (2 * wm + kh) * 36
                                   + mt * 16 + gq + joff;
                    unsigned ah[4], al[4];
                    ah[0] = __float_as_uint(sAh[ab]);
                    ah[1] = __float_as_uint(sAh[ab + 8]);
                    ah[2] = __float_as_uint(sAh[ab + 1440]);
                    ah[3] = __float_as_uint(sAh[ab + 1448]);
                    al[0] = __float_as_uint(sAl[ab]);
                    al[1] = __float_as_uint(sAl[ab + 8]);
                    al[2] = __float_as_uint(sAl[ab + 1440]);
                    al[3] = __float_as_uint(sAl[ab + 1448]);
#pragma unroll
                    for (int nt = 0; nt < 4; nt++) mma_tf32(acc[mt][nt], ah, bh + 2*nt);
#pragma unroll
                    for (int nt = 0; nt < 4; nt++) mma_tf32(acc[mt][nt], ah, bl + 2*nt);
#pragma unroll
                    for (int nt = 0; nt < 4; nt++) mma_tf32(acc[mt][nt], al, bh + 2*nt);
                }
            }
            __syncthreads();
        }
    }

    const int gr = r0 + wm;
#pragma unroll
    for (int mt = 0; mt < 2; mt++) {
        const int cb = mt * 16 + gq;
#pragma unroll
        for (int nt = 0; nt < 4; nt++) {
            const int ocb = oc0 + wn + nt * 8 + 2 * tg;
            float bv0 = bias[ocb];
            float bv1 = bias[ocb + 1];
            float d0 = acc[mt][nt][0] + bv0;
            float d1 = acc[mt][nt][1] + bv1;
            float d2 = acc[mt][nt][2] + bv0;
            float d3 = acc[mt][nt][3] + bv1;
            if (POST) {
                d0 = fmaxf(d0, 0.f); d1 = fmaxf(d1, 0.f);
                d2 = fmaxf(d2, 0.f); d3 = fmaxf(d3, 0.f);
            }
            float* o0 = out + ((size_t)(n * COUT + ocb)) * 1024 + gr * 32;
            float* o1 = o0 + 1024;
            o0[cb]     = d0;
            o1[cb]     = d1;
            o0[cb + 8] = d2;
            o1[cb + 8] = d3;
        }
    }
}

// ---------------------------------------------------------------------------
// ConvTranspose 4x4 s2 p1 (32x32 -> 64x64) via split-TF32 mma.
// Parity decomposition: class (po,pw) is a 2x2-tap stride-1 conv.
// grid(COUT/64, 32 = 8 rowtiles x 4 classes, B), block 256.
// A layout identical to conv3x3 ([8ci][6r][36c]); B = 32 rows x 72.
// ---------------------------------------------------------------------------
#define BT_PLANE (32*72)               // 2304
#define SMT_BYTES ((2*A_PLANE + 2*BT_PLANE) * 4)   // 32256

template<int CIN, int COUT, bool PRE, bool POST>
__global__ void __launch_bounds__(256, 2) convT_mma_k(
    const float* __restrict__ in, const float* __restrict__ wh,
    const float* __restrict__ wl, const float* __restrict__ bias,
    float* __restrict__ out)
{
    extern __shared__ float smx[];
    float* sAh = smx;
    float* sAl = smx + A_PLANE;
    float* sBh = smx + 2 * A_PLANE;
    float* sBl = smx + 2 * A_PLANE + BT_PLANE;

    const int n    = blockIdx.z;
    const int oc0  = blockIdx.x * 64;
    const int cls  = blockIdx.y & 3;
    const int r0   = (blockIdx.y >> 2) * 4;   // oh' base (of 32)
    const int po   = cls >> 1;
    const int pw   = cls & 1;
    const int tid  = threadIdx.x;
    const int warp = tid >> 5;
    const int lane = tid & 31;
    const int wm   = warp >> 1;
    const int wn   = (warp & 1) * 32;
    const int gq   = lane >> 2;
    const int tg   = lane & 3;

    const float* inp = in + (size_t)n * CIN * 1024;

    float acc[2][4][4];
#pragma unroll
    for (int mt = 0; mt < 2; mt++)
#pragma unroll
        for (int nt = 0; nt < 4; nt++)
#pragma unroll
            for (int i = 0; i < 4; i++) acc[mt][nt][i] = 0.f;

    const int NCH = CIN / 8;
    for (int ch = 0; ch < NCH; ch++) {
        const int ci0 = ch * 8;

        for (int idx = tid; idx < A_PLANE; idx += 256) {
            int ci  = idx / 216;
            int rem = idx - ci * 216;
            int r   = rem / 36;
            int c   = rem - r * 36;
            int ih  = r0 - 1 + r;
            int iw  = c - 1;
            float v = 0.f;
            if (c < 34 && (unsigned)ih < 32u && (unsigned)iw < 32u)
                v = inp[(size_t)(ci0 + ci) * 1024 + ih * 32 + iw];
            if (PRE) v = fmaxf(v, 0.f);
            float hi = tf32_rna(v);
            sAh[idx] = hi;
            sAl[idx] = tf32_rna(v - hi);
        }

        for (int idx = tid; idx < 512; idx += 256) {
            int row = idx >> 4;
            int c4  = idx & 15;
            int tap = row >> 3;
            int ci  = row & 7;
            size_t g = (size_t)((cls * 4 + tap) * CIN + ci0 + ci) * COUT + oc0 + 4 * c4;
            int s = row * 72 + 4 * c4;
            *reinterpret_cast<float4*>(sBh + s) =
                *reinterpret_cast<const float4*>(wh + g);
            *reinterpret_cast<float4*>(sBl + s) =
                *reinterpret_cast<const float4*>(wl + g);
        }
        __syncthreads();

#pragma unroll
        for (int tap = 0; tap < 4; tap++) {
            const int khi = tap >> 1, kwi = tap & 1;
            const int rloc = wm + 1 + (po ? (1 - khi) : -khi);
            const int cloc = 1 + (pw ? (1 - kwi) : -kwi);
            unsigned bh[8], bl[8];
            const int bbase = (tap * 8 + tg) * 72 + wn + gq;
#pragma unroll
            for (int nt = 0; nt < 4; nt++) {
                bh[2*nt]   = __float_as_uint(sBh[bbase + 8 * nt]);
                bh[2*nt+1] = __float_as_uint(sBh[bbase + 288 + 8 * nt]);
                bl[2*nt]   = __float_as_uint(sBl[bbase + 8 * nt]);
                bl[2*nt+1] = __float_as_uint(sBl[bbase + 288 + 8 * nt]);
            }
#pragma unroll
            for (int mt = 0; mt < 2; mt++) {
                const int ab = tg * 216 + rloc * 36 + mt * 16 + gq + cloc;
                unsigned ah[4], al[4];
                ah[0] = __float_as_uint(sAh[ab]);
                ah[1] = __float_as_uint(sAh[ab + 8]);
                ah[2] = __float_as_uint(sAh[ab + 864]);
                ah[3] = __float_as_uint(sAh[ab + 872]);
                al[0] = __float_as_uint(sAl[ab]);
                al[1] = __float_as_uint(sAl[ab + 8]);
                al[2] = __float_as_uint(sAl[ab + 864]);
                al[3] = __float_as_uint(sAl[ab + 872]);
#pragma unroll
                for (int nt = 0; nt < 4; nt++) mma_tf32(acc[mt][nt], ah, bh + 2*nt);
#pragma unroll
                for (int nt = 0; nt < 4; nt++) mma_tf32(acc[mt][nt], ah, bl + 2*nt);
#pragma unroll
                for (int nt = 0; nt < 4; nt++) mma_tf32(acc[mt][nt], al, bh + 2*nt);
            }
        }
        __syncthreads();
    }

    const int gr = 2 * (r0 + wm) + po;          // output row (of 64)
#pragma unroll
    for (int mt = 0; mt < 2; mt++) {
        const int cb = mt * 16 + gq;
#pragma unroll
        for (int nt = 0; nt < 4; nt++) {
            const int ocb = oc0 + wn + nt * 8 + 2 * tg;
            float bv0 = bias[ocb];
            float bv1 = bias[ocb + 1];
            float d0 = acc[mt][nt][0] + bv0;
            float d1 = acc[mt][nt][1] + bv1;
            float d2 = acc[mt][nt][2] + bv0;
            float d3 = acc[mt][nt][3] + bv1;
            if (POST) {
                d0 = fmaxf(d0, 0.f); d1 = fmaxf(d1, 0.f);
                d2 = fmaxf(d2, 0.f); d3 = fmaxf(d3, 0.f);
            }
            float* o0 = out + ((size_t)(n * COUT + ocb)) * 4096 + gr * 64;
            float* o1 = o0 + 4096;
            o0[2 * cb + pw]      = d0;
            o1[2 * cb + pw]      = d1;
            o0[2 * cb + 16 + pw] = d2;
            o1[2 * cb + 16 + pw] = d3;
        }
    }
}

// ---------------------------------------------------------------------------
// 4x4 stride-2 pad-1 conv, f32x2 packed (enc1 only, CIN=3).
// ---------------------------------------------------------------------------
template<int CIN, int COUT, int HIN, int HOUT, bool POST>
__global__ void __launch_bounds__(128, 3) conv4x4s2_k(
    const float* __restrict__ in, const float* __restrict__ w,
    const float* __restrict__ bias, float* __restrict__ out)
{
    extern __shared__ char dsm[];
    ull*   s_w2  = (ull*)dsm;
    float* s_in0 = (float*)(dsm + (size_t)CIN * 4 * 16 * 8);
    float* s_in1 = s_in0 + 66 * 66;

    const int n   = blockIdx.z;
    const int oc0 = blockIdx.x * 4;
    const int TB  = HOUT / 32;
    const int r0  = (blockIdx.y / TB) * 32;
    const int c0  = (blockIdx.y % TB) * 32;
    const int tid = threadIdx.x;
    const int loh0 = (tid >> 3) * 2;
    const int low0 = (tid & 7) * 4;

    for (int i = tid; i < 4 * CIN * 16; i += 128) {
        int oc = i / (CIN * 16);
        int r  = i - oc * (CIN * 16);
        int ci = r / 16, kk = r - ci * 16;
        float v = w[(size_t)(oc0 + oc) * CIN * 16 + r];
        s_w2[(ci * 4 + oc) * 16 + kk] = pk2(v, v);
    }

    const int ihb = 2 * r0 - 1, iwb = 2 * c0 - 1;
    const float* inp = in + (size_t)n * CIN * HIN * HIN;

    for (int idx = tid; idx < 66 * 66; idx += 128) {
        int r = idx / 66, c = idx - r * 66;
        int ih = ihb + r, iw = iwb + c;
        float v = 0.f;
        if ((unsigned)ih < (unsigned)HIN && (unsigned)iw < (unsigned)HIN)
            v = inp[(size_t)ih * HIN + iw];
        s_in0[idx] = v;
    }
    __syncthreads();

    ull acc[4][4];
#pragma unroll
    for (int a = 0; a < 4; a++)
#pragma unroll
        for (int q = 0; q < 4; q++) acc[a][q] = 0ULL;

    for (int ci = 0; ci < CIN; ci++) {
        const float* cur = (ci & 1) ? s_in1 : s_in0;
        if (ci + 1 < CIN) {
            float* nb = ((ci + 1) & 1) ? s_in1 : s_in0;
            const float* inn = inp + (size_t)(ci + 1) * HIN * HIN;
            for (int idx = tid; idx < 66 * 66; idx += 128) {
                int r = idx / 66, c = idx - r * 66;
                int ih = ihb + r, iw = iwb + c;
                float v = 0.f;
                if ((unsigned)ih < (unsigned)HIN && (unsigned)iw < (unsigned)HIN)
                    v = inn[(size_t)ih * HIN + iw];
                nb[idx] = v;
            }
        }

        const int rowA0 = 2 * loh0;
        const int base  = 2 * low0;
        const ull* wci  = s_w2 + ci * 64;
#pragma unroll
        for (int kh = 0; kh < 4; kh++) {
            const float* pa = cur + (rowA0 + kh) * 66 + base;
            const float* pb = pa + 132;
            ull P[10];
#pragma unroll
            for (int c = 0; c < 10; c++) P[c] = pk2(pa[c], pb[c]);
#pragma unroll
            for (int oc = 0; oc < 4; oc++)
#pragma unroll
                for (int kw = 0; kw < 4; kw++) {
                    ull w2 = wci[oc * 16 + kh * 4 + kw];
#pragma unroll
                    for (int pw = 0; pw < 4; pw++)
                        fma2(acc[oc][pw], P[2 * pw + kw], w2);
                }
        }
        __syncthreads();
    }

#pragma unroll
    for (int oc = 0; oc < 4; oc++) {
        float bv = bias[oc0 + oc];
        float* obase = out + ((size_t)(n * COUT + oc0 + oc)) * HOUT * HOUT +
                       (size_t)(r0 + loh0) * HOUT + (c0 + low0);
#pragma unroll
        for (int pw = 0; pw < 4; pw++) {
            float2 v = unpk(acc[oc][pw]);
            v.x += bv; v.y += bv;
            if (POST) { v.x = fmaxf(v.x, 0.f); v.y = fmaxf(v.y, 0.f); }
            obase[pw]        = v.x;
            obase[HOUT + pw] = v.y;
        }
    }
}

// ---------------------------------------------------------------------------
// ConvTranspose2d k=4 s=2 p=1, f32x2 packed (tc2 only).
// ---------------------------------------------------------------------------
template<int CIN, int COUT, int OCB, int HIN, int HOUT, bool PRE, bool POST>
__global__ void __launch_bounds__(128, 4) convT4x4s2_k(
    const float* __restrict__ in, const float* __restrict__ w,
    const float* __restrict__ bias, float* __restrict__ out)
{
    const int n   = blockIdx.z;
    const int oc0 = blockIdx.x * OCB;
    const int TB  = HOUT / 32;
    const int r0  = (blockIdx.y / TB) * 32;
    const int c0  = (blockIdx.y % TB) * 32;
    const int tid = threadIdx.x;
    const int loh0 = (tid >> 3) * 2;
    const int low0 = (tid & 7) * 4;

    __shared__ float s_in[2][18 * 18];
    __shared__ ull   s_w2[CIN * OCB * 8];

    for (int i = tid; i < CIN * OCB * 8; i += 128) {
        int per = OCB * 8;
        int ci = i / per;
        int r  = i - ci * per;
        int oc = r >> 3;
        int t  = r & 7;
        int kw = t >> 1, p = t & 1;
        const float* wb = w + ((size_t)ci * COUT + oc0 + oc) * 16;
        s_w2[i] = pk2(wb[(p * 2 + 1) * 4 + kw], wb[(p * 2) * 4 + kw]);
    }

    const int ihb = (r0 - 2) / 2;
    const int iwb = (c0 - 2) / 2;
    const float* inp = in + (size_t)n * CIN * HIN * HIN;

    int goff[3];
#pragma unroll
    for (int s = 0; s < 3; s++) {
        int idx = tid + s * 128;
        int r = idx / 18, c = idx - r * 18;
        int ih = ihb + r, iw = iwb + c;
        goff[s] = ((unsigned)ih < (unsigned)HIN && (unsigned)iw < (unsigned)HIN)
                      ? ih * HIN + iw : -1;
    }

    {
        float* b0 = s_in[0];
#pragma unroll
        for (int s = 0; s < 2; s++) {
            float v = (goff[s] >= 0) ? inp[goff[s]] : 0.f;
            if (PRE) v = fmaxf(v, 0.f);
            b0[tid + s * 128] = v;
        }
        if (tid < 68) {
            float v = (goff[2] >= 0) ? inp[goff[2]] : 0.f;
            if (PRE) v = fmaxf(v, 0.f);
            b0[tid + 256] = v;
        }
    }
    __syncthreads();

    ull acc[OCB][4];
#pragma unroll
    for (int a = 0; a < OCB; a++)
#pragma unroll
        for (int q = 0; q < 4; q++) acc[a][q] = 0ULL;

    const int rb = loh0 >> 1;
    const int cb = low0 >> 1;

    for (int ci = 0; ci < CIN; ci++) {
        const float* cur = s_in[ci & 1];
        if (ci + 1 < CIN) {
            const float* inn = inp + (size_t)(ci + 1) * HIN * HIN;
            float* nb = s_in[(ci + 1) & 1];
#pragma unroll
            for (int s = 0; s < 2; s++) {
                float v = (goff[s] >= 0) ? inn[goff[s]] : 0.f;
                if (PRE) v = fmaxf(v, 0.f);
                nb[tid + s * 128] = v;
            }
            if (tid < 68) {
                float v = (goff[2] >= 0) ? inn[goff[2]] : 0.f;
                if (PRE) v = fmaxf(v, 0.f);
                nb[tid + 256] = v;
            }
        }

        ull A[4], B[4];
#pragma unroll
        for (int c = 0; c < 4; c++) {
            float x0 = cur[rb * 18 + cb + c];
            float x1 = cur[(rb + 1) * 18 + cb + c];
            float x2 = cur[(rb + 2) * 18 + cb + c];
            A[c] = pk2(x1, x2);
            B[c] = pk2(x0, x1);
        }

        const ull* wci = s_w2 + ci * OCB * 8;
#pragma unroll
        for (int oc = 0; oc < OCB; oc++) {
            const ull* wp = wci + oc * 8;
#pragma unroll
            for (int pw = 0; pw < 4; pw++) {
                const int kwh = (pw & 1) ? 0 : 1;
                const int rh  = (pw >> 1) + 1 + (pw & 1);
                fma2(acc[oc][pw], A[rh],     wp[kwh * 2 + 0]);
                fma2(acc[oc][pw], B[rh],     wp[kwh * 2 + 1]);
                fma2(acc[oc][pw], A[rh - 1], wp[(kwh + 2) * 2 + 0]);
                fma2(acc[oc][pw], B[rh - 1], wp[(kwh + 2) * 2 + 1]);
            }
        }
        __syncthreads();
    }

#pragma unroll
    for (int oc = 0; oc < OCB; oc++) {
        float bv = bias[oc0 + oc];
        float* obase = out + ((size_t)(n * COUT + oc0 + oc)) * HOUT * HOUT +
                       (size_t)(r0 + loh0) * HOUT + (c0 + low0);
#pragma unroll
        for (int pw = 0; pw < 4; pw++) {
            float2 v = unpk(acc[oc][pw]);
            v.x += bv; v.y += bv;
            if (POST) { v.x = fmaxf(v.x, 0.f); v.y = fmaxf(v.y, 0.f); }
            obase[pw]        = v.x;
            obase[HOUT + pw] = v.y;
        }
    }
}

// ---------------------------------------------------------------------------
// 1x1 conv on 32x32 images.
// ---------------------------------------------------------------------------
template<int CIN, int COUT, bool PRE, bool BIAS, bool ADDRES>
__global__ void __launch_bounds__(256) conv1x1_k(
    const float* __restrict__ in, const float* __restrict__ w,
    const float* __restrict__ bias, float* __restrict__ out)
{
    const int n   = blockIdx.y;
    const int oc0 = blockIdx.x * 4;
    const int tid = threadIdx.x;
    const int hw0 = tid * 4;

    __shared__ float s_w[4 * CIN];
    for (int i = tid; i < 4 * CIN; i += 256)
        s_w[i] = w[(oc0 + i / CIN) * CIN + (i % CIN)];
    __syncthreads();

    float acc[4][4];
#pragma unroll
    for (int a = 0; a < 4; a++)
#pragma unroll
        for (int q = 0; q < 4; q++) acc[a][q] = 0.f;

    const float* inp = in + (size_t)n * CIN * 1024 + hw0;
    for (int ci = 0; ci < CIN; ci++) {
        float4 v = *reinterpret_cast<const float4*>(inp + (size_t)ci * 1024);
        if (PRE) {
            v.x = fmaxf(v.x, 0.f); v.y = fmaxf(v.y, 0.f);
            v.z = fmaxf(v.z, 0.f); v.w = fmaxf(v.w, 0.f);
        }
#pragma unroll
        for (int oc = 0; oc < 4; oc++) {
            float wv = s_w[oc * CIN + ci];
            acc[oc][0] = fmaf(v.x, wv, acc[oc][0]);
            acc[oc][1] = fmaf(v.y, wv, acc[oc][1]);
            acc[oc][2] = fmaf(v.z, wv, acc[oc][2]);
            acc[oc][3] = fmaf(v.w, wv, acc[oc][3]);
        }
    }

#pragma unroll
    for (int oc = 0; oc < 4; oc++) {
        float bv = BIAS ? bias[oc0 + oc] : 0.f;
        float* op = out + ((size_t)(n * COUT + oc0 + oc)) * 1024 + hw0;
        float4 o;
        o.x = acc[oc][0] + bv; o.y = acc[oc][1] + bv;
        o.z = acc[oc][2] + bv; o.w = acc[oc][3] + bv;
        if (ADDRES) {
            float4 r = *reinterpret_cast<const float4*>(op);
            o.x += r.x; o.y += r.y; o.z += r.z; o.w += r.w;
        }
        *reinterpret_cast<float4*>(op) = o;
    }
}

// ---------------------------------------------------------------------------
// Vector quantizer.
// ---------------------------------------------------------------------------
#define VQ_SMEM ((32768 + 512 + 512 + 256) * 4)

__global__ void __launch_bounds__(256) vq_k(
    const float* __restrict__ ze, const float* __restrict__ E,
    float* __restrict__ zq, int* __restrict__ hist, float* __restrict__ mse)
{
    extern __shared__ float sm[];
    float* sE   = sm;
    float* sEsq = sm + 32768;
    int*   sHist= (int*)(sm + 33280);
    float* sRed = sm + 33792;

    const int tid = threadIdx.x;
    for (int i = tid; i < VQ_K * VQ_D; i += 256) sE[i] = E[i];
    for (int i = tid; i < VQ_K; i += 256) sHist[i] = 0;
    __syncthreads();
    for (int i = tid; i < VQ_K; i += 256) {
        const float* e = &sE[i * VQ_D];
        float s = 0.f;
#pragma unroll 16
        for (int d = 0; d < VQ_D; d++) s = fmaf(e[d], e[d], s);
        sEsq[i] = s;
    }
    __syncthreads();

    const int p  = blockIdx.x * 256 + tid;
    const int n  = p >> 10;
    const int hw = p & 1023;
    const float* zp = ze + (size_t)n * VQ_D * 1024 + hw;

    float f[VQ_D];
#pragma unroll
    for (int d = 0; d < VQ_D; d++) f[d] = zp[(size_t)d * 1024];

    float best = 3.4e38f;
    int   bi   = 0;
    for (int k = 0; k < VQ_K; k++) {
        const float4* e4 = reinterpret_cast<const float4*>(&sE[k * VQ_D]);
        float s0 = 0.f, s1 = 0.f, s2 = 0.f, s3 = 0.f;
#pragma unroll
        for (int d = 0; d < VQ_D / 4; d++) {
            float4 e = e4[d];
            s0 = fmaf(e.x, f[4 * d + 0], s0);
            s1 = fmaf(e.y, f[4 * d + 1], s1);
            s2 = fmaf(e.z, f[4 * d + 2], s2);
            s3 = fmaf(e.w, f[4 * d + 3], s3);
        }
        float score = sEsq[k] - 2.f * ((s0 + s1) + (s2 + s3));
        if (score < best) { best = score; bi = k; }
    }

    const float* eb = &sE[bi * VQ_D];
    float* zqp = zq + (size_t)n * VQ_D * 1024 + hw;
    float md = 0.f;
#pragma unroll
    for (int d = 0; d < VQ_D; d++) {
        float ev = eb[d];
        float dd = f[d] - ev;
        md = fmaf(dd, dd, md);
        zqp[(size_t)d * 1024] = ev;
    }

    atomicAdd(&sHist[bi], 1);
    sRed[tid] = md;
    __syncthreads();
    for (int s = 128; s > 0; s >>= 1) {
        if (tid < s) sRed[tid] += sRed[tid + s];
        __syncthreads();
    }
    if (tid == 0) atomicAdd(mse, sRed[0]);
    for (int i = tid; i < VQ_K; i += 256) {
        int c = sHist[i];
        if (c) atomicAdd(&hist[i], c);
    }
}

__global__ void finalize_k(const int* __restrict__ hist,
                           const float* __restrict__ mse,
                           float* __restrict__ out)
{
    __shared__ float red[VQ_K];
    const int k = threadIdx.x;
    float pb = (float)hist[k] * (1.f / 65536.f);
    red[k] = pb * log2f(pb + 1e-10f);
    __syncthreads();
    for (int s = 256; s > 0; s >>= 1) {
        if (k < s) red[k] += red[k + s];
        __syncthreads();
    }
    if (k == 0) {
        float H = -red[0];
        float m = mse[0] * (1.f / (65536.f * 64.f));
        out[0]       = 1.25f * m;
        out[OUT_ELQ] = m;
        out[OUT_QLQ] = m;
        out[OUT_EW]  = exp2f(H);
    }
}

// ---------------------------------------------------------------------------
// Launch
// ---------------------------------------------------------------------------
extern "C" void kernel_launch(void* const* d_in, const int* in_sizes, int n_in,
                              void* d_out, int out_size)
{
    (void)in_sizes; (void)n_in; (void)out_size;
    const float* x          = (const float*)d_in[0];
    const float* enc_w1     = (const float*)d_in[1];
    const float* enc_b1     = (const float*)d_in[2];
    const float* enc_w2     = (const float*)d_in[3];
    const float* enc_b2     = (const float*)d_in[4];
    const float* enc_w3     = (const float*)d_in[5];
    const float* enc_b3     = (const float*)d_in[6];
    const float* enc_w4     = (const float*)d_in[7];
    const float* enc_b4     = (const float*)d_in[8];
    const float* enc_res_w1 = (const float*)d_in[9];
    const float* enc_res_w2 = (const float*)d_in[10];
    const float* enc_adj_w  = (const float*)d_in[11];
    const float* enc_adj_b  = (const float*)d_in[12];
    const float* E          = (const float*)d_in[13];
    const float* dec_adj_w  = (const float*)d_in[14];
    const float* dec_adj_b  = (const float*)d_in[15];
    const float* dec_res_w1 = (const float*)d_in[16];
    const float* dec_res_w2 = (const float*)d_in[17];
    const float* tc1_w      = (const float*)d_in[18];
    const float* tc1_b      = (const float*)d_in[19];
    const float* tc2_w      = (const float*)d_in[20];
    const float* tc2_b      = (const float*)d_in[21];
    float* out = (float*)d_out;

    float *h1, *a, *b, *mid, *ze, *zq, *mse, *wh, *wl; int* hist;
    cudaGetSymbolAddress((void**)&h1,  g_h1);
    cudaGetSymbolAddress((void**)&a,   g_a);
    cudaGetSymbolAddress((void**)&b,   g_b);
    cudaGetSymbolAddress((void**)&mid, g_mid);
    cudaGetSymbolAddress((void**)&ze,  g_ze);
    cudaGetSymbolAddress((void**)&zq,  g_zq);
    cudaGetSymbolAddress((void**)&wh,  g_wh);
    cudaGetSymbolAddress((void**)&wl,  g_wl);
    cudaGetSymbolAddress((void**)&mse, g_mse);
    cudaGetSymbolAddress((void**)&hist, g_hist);

    cudaFuncSetAttribute(vq_k, cudaFuncAttributeMaxDynamicSharedMemorySize, VQ_SMEM);

    const int SMEM_C1 = 3 * 4 * 16 * 8 + 2 * 66 * 66 * 4;   // 36384
    cudaFuncSetAttribute(conv4x4s2_k<3, 64, 128, 64, true>,
                         cudaFuncAttributeMaxDynamicSharedMemorySize, SMEM_C1);

    cudaFuncSetAttribute(conv3x3_mma_k<128, 128, false, true,  true>,
                         cudaFuncAttributeMaxDynamicSharedMemorySize, SM3_BYTES);
    cudaFuncSetAttribute(conv3x3_mma_k<128, 128, false, false, true>,
                         cudaFuncAttributeMaxDynamicSharedMemorySize, SM3_BYTES);
    cudaFuncSetAttribute(conv3x3_mma_k<128, 64, true, true, false>,
                         cudaFuncAttributeMaxDynamicSharedMemorySize, SM3_BYTES);
    cudaFuncSetAttribute(conv3x3_mma_k<64, 128, false, false, true>,
                         cudaFuncAttributeMaxDynamicSharedMemorySize, SM3_BYTES);
    cudaFuncSetAttribute(conv4x4s2_mma_k<64, 128, true>,
                         cudaFuncAttributeMaxDynamicSharedMemorySize, SM4_BYTES);
    cudaFuncSetAttribute(convT_mma_k<128, 64, true, true>,
                         cudaFuncAttributeMaxDynamicSharedMemorySize, SMT_BYTES);

    reset_k<<<1, 512>>>(hist, mse);

    // ---- Encoder ----
    conv4x4s2_k<3, 64, 128, 64, true><<<dim3(16, 4, BATCH), 128, SMEM_C1>>>(x, enc_w1, enc_b1, h1);

    wsplit4_k<<<288, 256>>>(enc_w2, 64, 128, wh, wl);
    conv4x4s2_mma_k<64, 128, true><<<dim3(2, 8, BATCH), 256, SM4_BYTES>>>(h1, wh, wl, enc_b2, a);

    wsplit_k<<<288, 256>>>(enc_w3, 128, 128, wh, wl);
    conv3x3_mma_k<128, 128, false, true,  true><<<dim3(2, 8, BATCH), 256, SM3_BYTES>>>(a, wh, wl, enc_b3, b);
    wsplit_k<<<288, 256>>>(enc_w4, 128, 128, wh, wl);
    conv3x3_mma_k<128, 128, false, false, true><<<dim3(2, 8, BATCH), 256, SM3_BYTES>>>(b, wh, wl, enc_b4, a);
    wsplit_k<<<288, 256>>>(enc_res_w1, 128, 64, wh, wl);
    conv3x3_mma_k<128, 64, true, true, false><<<dim3(1, 8, BATCH), 256, SM3_BYTES>>>(a, wh, wl, nullptr, mid);
    conv1x1_k<64, 128, false, false, true><<<dim3(32, BATCH), 256>>>(mid, enc_res_w2, nullptr, a);
    wsplit_k<<<288, 256>>>(enc_res_w1 + 64 * 128 * 9, 128, 64, wh, wl);
    conv3x3_mma_k<128, 64, true, true, false><<<dim3(1, 8, BATCH), 256, SM3_BYTES>>>(a, wh, wl, nullptr, mid);
    conv1x1_k<64, 128, false, false, true><<<dim3(32, BATCH), 256>>>(mid, enc_res_w2 + 128 * 64, nullptr, a);
    conv1x1_k<128, 64, true, true, false><<<dim3(16, BATCH), 256>>>(a, enc_adj_w, enc_adj_b, ze);

    // ---- Vector quantizer ----
    vq_k<<<256, 256, VQ_SMEM>>>(ze, E, zq, hist, mse);
    finalize_k<<<1, 512>>>(hist, mse, out);

    // ---- Decoder ----
    wsplit_k<<<288, 256>>>(dec_adj_w, 64, 128, wh, wl);
    conv3x3_mma_k<64, 128, false, false, true><<<dim3(2, 8, BATCH), 256, SM3_BYTES>>>(zq, wh, wl, dec_adj_b, a);
    wsplit_k<<<288, 256>>>(dec_res_w1, 128, 64, wh, wl);
    conv3x3_mma_k<128, 64, true, true, false><<<dim3(1, 8, BATCH), 256, SM3_BYTES>>>(a, wh, wl, nullptr, mid);
    conv1x1_k<64, 128, false, false, true><<<dim3(32, BATCH), 256>>>(mid, dec_res_w2, nullptr, a);
    wsplit_k<<<288, 256>>>(dec_res_w1 + 64 * 128 * 9, 128, 64, wh, wl);
    conv3x3_mma_k<128, 64, true, true, false><<<dim3(1, 8, BATCH), 256, SM3_BYTES>>>(a, wh, wl, nullptr, mid);
    conv1x1_k<64, 128, false, false, true><<<dim3(32, BATCH), 256>>>(mid, dec_res_w2 + 128 * 64, nullptr, a);

    wsplitT_k<<<288, 256>>>(tc1_w, 128, 64, wh, wl);
    convT_mma_k<128, 64, true, true><<<dim3(1, 32, BATCH), 256, SMT_BYTES>>>(a, wh, wl, tc1_b, h1);

    convT4x4s2_k<64, 3, 3, 64, 128, false, false><<<dim3(1, 16, BATCH), 128>>>(h1, tc2_w, tc2_b, out + OUT_RECON_OFF);
}